// round 1
// baseline (speedup 1.0000x reference)
#include <cuda_runtime.h>
#include <math.h>

#define NB 4
#define NS 2048
#define NHID 1024
#define NHEADS 16
#define DHEAD 64
#define MTOT (NB * NS)   // 8192

// Scratch (static device globals — no allocation APIs)
__device__ float g_q[NB * NHEADS * NS * DHEAD];
__device__ float g_k[NB * NHEADS * NS * DHEAD];
__device__ float g_v[NB * NHEADS * NS * DHEAD];
__device__ float g_attn[NB * NS * NHID];

// ---------------------------------------------------------------------------
// GEMM: C[m,n] = sum_k A[m,k] * W[n,k]   (i.e. A @ W^T), A:[M,1024], W:[1024,1024]
// Tile 128x128, K-step 8, 256 threads, 8x8 per thread.
// headMode=1: scatter C into [B, NH, S, HD] layout (n -> h*64+d, m -> b*S+s).
// ---------------------------------------------------------------------------
__global__ __launch_bounds__(256)
void gemm_xwt_kernel(const float* __restrict__ A, const float* __restrict__ W,
                     float* __restrict__ C, int headMode)
{
    __shared__ float As[8][128];
    __shared__ float Bs[8][128];

    const int t  = threadIdx.x;
    const int tx = t & 15;
    const int ty = t >> 4;
    const int m0 = blockIdx.y << 7;
    const int n0 = blockIdx.x << 7;

    const int ldRow = t >> 1;          // 0..127
    const int ldK   = (t & 1) << 2;    // 0 or 4

    const float* Ap = A + (size_t)(m0 + ldRow) * NHID + ldK;
    const float* Wp = W + (size_t)(n0 + ldRow) * NHID + ldK;

    float acc[8][8];
#pragma unroll
    for (int i = 0; i < 8; i++)
#pragma unroll
        for (int j = 0; j < 8; j++) acc[i][j] = 0.f;

    for (int k0 = 0; k0 < NHID; k0 += 8) {
        float4 av = *(const float4*)(Ap + k0);
        float4 wv = *(const float4*)(Wp + k0);
        __syncthreads();
        As[ldK + 0][ldRow] = av.x; As[ldK + 1][ldRow] = av.y;
        As[ldK + 2][ldRow] = av.z; As[ldK + 3][ldRow] = av.w;
        Bs[ldK + 0][ldRow] = wv.x; Bs[ldK + 1][ldRow] = wv.y;
        Bs[ldK + 2][ldRow] = wv.z; Bs[ldK + 3][ldRow] = wv.w;
        __syncthreads();
#pragma unroll
        for (int kk = 0; kk < 8; kk++) {
            float a[8], b[8];
#pragma unroll
            for (int i = 0; i < 8; i++) a[i] = As[kk][ty + (i << 4)];
#pragma unroll
            for (int j = 0; j < 8; j++) b[j] = Bs[kk][tx + (j << 4)];
#pragma unroll
            for (int i = 0; i < 8; i++)
#pragma unroll
                for (int j = 0; j < 8; j++)
                    acc[i][j] = fmaf(a[i], b[j], acc[i][j]);
        }
    }

    if (headMode) {
#pragma unroll
        for (int i = 0; i < 8; i++) {
            int m = m0 + ty + (i << 4);
            int b = m >> 11;            // S = 2048
            int s = m & (NS - 1);
#pragma unroll
            for (int j = 0; j < 8; j++) {
                int n = n0 + tx + (j << 4);
                int h = n >> 6;
                int d = n & 63;
                C[((((size_t)(b * NHEADS + h)) * NS + s) << 6) + d] = acc[i][j];
            }
        }
    } else {
#pragma unroll
        for (int i = 0; i < 8; i++) {
            int m = m0 + ty + (i << 4);
#pragma unroll
            for (int j = 0; j < 8; j++) {
                int n = n0 + tx + (j << 4);
                C[(size_t)m * NHID + n] = acc[i][j];
            }
        }
    }
}

// ---------------------------------------------------------------------------
// Flash attention: one CTA = one (b,h) and one 128-row Q tile.
// Streams K/V in 64-row tiles with online softmax. All fp32.
// Smem: Qs[128][68] + Ks[64][68] + Vt[64][68] + Ps[128][68] + msk[64]
// ---------------------------------------------------------------------------
#define QROWS 128
#define KROWS 64
#define LDP 68   // padded row stride (floats)

#define ATTN_SMEM_FLOATS (QROWS*LDP + KROWS*LDP + KROWS*LDP + QROWS*LDP + 64)
#define ATTN_SMEM_BYTES  (ATTN_SMEM_FLOATS * 4)

__global__ __launch_bounds__(256)
void attn_kernel(const float* __restrict__ mask)
{
    extern __shared__ float sm[];
    float* Qs  = sm;                       // 128 x 68
    float* Ks  = Qs + QROWS * LDP;         //  64 x 68
    float* Vt  = Ks + KROWS * LDP;         //  64 x 68 (transposed: [d][k])
    float* Ps  = Vt + KROWS * LDP;         // 128 x 68
    float* msk = Ps + QROWS * LDP;         //  64

    const int t  = threadIdx.x;
    const int tx = t & 15;
    const int ty = t >> 4;

    const int bh = blockIdx.y;             // 0..63
    const int b  = bh >> 4;
    const int h  = bh & 15;
    const int q0 = blockIdx.x << 7;

    const float* qp = g_q + ((size_t)bh * NS + q0) * DHEAD;
    const float* kp = g_k + (size_t)bh * NS * DHEAD;
    const float* vp = g_v + (size_t)bh * NS * DHEAD;

    // Load Q tile (128 x 64), float4-coalesced
    for (int i = t; i < QROWS * 16; i += 256) {
        int r  = i >> 4;
        int c4 = (i & 15) << 2;
        float4 v = *(const float4*)&qp[r * DHEAD + c4];
        Qs[r * LDP + c4 + 0] = v.x; Qs[r * LDP + c4 + 1] = v.y;
        Qs[r * LDP + c4 + 2] = v.z; Qs[r * LDP + c4 + 3] = v.w;
    }

    float mrow[8], lrow[8], o[8][4];
#pragma unroll
    for (int i = 0; i < 8; i++) {
        mrow[i] = -INFINITY;
        lrow[i] = 0.f;
#pragma unroll
        for (int j = 0; j < 4; j++) o[i][j] = 0.f;
    }

    const float scaling = 0.125f;  // HD^-0.5

    for (int kt = 0; kt < NS; kt += KROWS) {
        __syncthreads();  // prior PV reads of Vt/Ps done before overwrite

        // Load K tile [64][64] and V tile transposed into Vt[d][k]
        for (int i = t; i < KROWS * 16; i += 256) {
            int r  = i >> 4;
            int c4 = (i & 15) << 2;
            float4 kv = *(const float4*)&kp[(kt + r) * DHEAD + c4];
            Ks[r * LDP + c4 + 0] = kv.x; Ks[r * LDP + c4 + 1] = kv.y;
            Ks[r * LDP + c4 + 2] = kv.z; Ks[r * LDP + c4 + 3] = kv.w;
            float4 vv = *(const float4*)&vp[(kt + r) * DHEAD + c4];
            Vt[(c4 + 0) * LDP + r] = vv.x; Vt[(c4 + 1) * LDP + r] = vv.y;
            Vt[(c4 + 2) * LDP + r] = vv.z; Vt[(c4 + 3) * LDP + r] = vv.w;
        }
        if (t < KROWS) msk[t] = mask[b * NS + kt + t];
        __syncthreads();

        // --- S = Q @ K^T, 128x64 tile, 8x4 per thread ---
        float s[8][4];
#pragma unroll
        for (int i = 0; i < 8; i++)
#pragma unroll
            for (int j = 0; j < 4; j++) s[i][j] = 0.f;

#pragma unroll
        for (int d4 = 0; d4 < DHEAD; d4 += 4) {
            float4 q4[8], k4[4];
#pragma unroll
            for (int i = 0; i < 8; i++)
                q4[i] = *(const float4*)&Qs[(ty + (i << 4)) * LDP + d4];
#pragma unroll
            for (int j = 0; j < 4; j++)
                k4[j] = *(const float4*)&Ks[(tx + (j << 4)) * LDP + d4];
#pragma unroll
            for (int i = 0; i < 8; i++)
#pragma unroll
                for (int j = 0; j < 4; j++) {
                    s[i][j] = fmaf(q4[i].x, k4[j].x, s[i][j]);
                    s[i][j] = fmaf(q4[i].y, k4[j].y, s[i][j]);
                    s[i][j] = fmaf(q4[i].z, k4[j].z, s[i][j]);
                    s[i][j] = fmaf(q4[i].w, k4[j].w, s[i][j]);
                }
        }

        // scale + additive mask
#pragma unroll
        for (int i = 0; i < 8; i++)
#pragma unroll
            for (int j = 0; j < 4; j++)
                s[i][j] = fmaf(s[i][j], scaling, msk[tx + (j << 4)]);

        // --- online softmax ---
        float tmax[8];
#pragma unroll
        for (int i = 0; i < 8; i++) {
            float m01 = fmaxf(s[i][0], s[i][1]);
            float m23 = fmaxf(s[i][2], s[i][3]);
            tmax[i] = fmaxf(m01, m23);
        }
#pragma unroll
        for (int off = 8; off >= 1; off >>= 1)
#pragma unroll
            for (int i = 0; i < 8; i++)
                tmax[i] = fmaxf(tmax[i], __shfl_xor_sync(0xffffffffu, tmax[i], off));

        float rs[8];
#pragma unroll
        for (int i = 0; i < 8; i++) {
            float mnew = fmaxf(mrow[i], tmax[i]);
            float corr = __expf(mrow[i] - mnew);
            mrow[i] = mnew;
            float r = 0.f;
#pragma unroll
            for (int j = 0; j < 4; j++) {
                float p = __expf(s[i][j] - mnew);
                r += p;
                Ps[(ty + (i << 4)) * LDP + tx + (j << 4)] = p;
            }
            rs[i] = r;
            lrow[i] = lrow[i] * corr;
#pragma unroll
            for (int j = 0; j < 4; j++) o[i][j] *= corr;
        }
#pragma unroll
        for (int off = 8; off >= 1; off >>= 1)
#pragma unroll
            for (int i = 0; i < 8; i++)
                rs[i] += __shfl_xor_sync(0xffffffffu, rs[i], off);
#pragma unroll
        for (int i = 0; i < 8; i++) lrow[i] += rs[i];

        __syncthreads();  // Ps visible to all

        // --- O += P @ V ---
#pragma unroll
        for (int k4 = 0; k4 < KROWS; k4 += 4) {
            float4 p4[8], v4[4];
#pragma unroll
            for (int i = 0; i < 8; i++)
                p4[i] = *(const float4*)&Ps[(ty + (i << 4)) * LDP + k4];
#pragma unroll
            for (int j = 0; j < 4; j++)
                v4[j] = *(const float4*)&Vt[(tx + (j << 4)) * LDP + k4];
#pragma unroll
            for (int i = 0; i < 8; i++)
#pragma unroll
                for (int j = 0; j < 4; j++) {
                    o[i][j] = fmaf(p4[i].x, v4[j].x, o[i][j]);
                    o[i][j] = fmaf(p4[i].y, v4[j].y, o[i][j]);
                    o[i][j] = fmaf(p4[i].z, v4[j].z, o[i][j]);
                    o[i][j] = fmaf(p4[i].w, v4[j].w, o[i][j]);
                }
        }
    }

    // Epilogue: normalize, store into [B, S, H] layout (h*64+d within hidden)
#pragma unroll
    for (int i = 0; i < 8; i++) {
        float inv = 1.f / lrow[i];
        int m = q0 + ty + (i << 4);
        size_t base = ((size_t)(b * NS) + m) * NHID + h * DHEAD;
#pragma unroll
        for (int j = 0; j < 4; j++) {
            int d = tx + (j << 4);
            g_attn[base + d] = o[i][j] * inv;
        }
    }
}

// ---------------------------------------------------------------------------
// Launch
// ---------------------------------------------------------------------------
extern "C" void kernel_launch(void* const* d_in, const int* in_sizes, int n_in,
                              void* d_out, int out_size)
{
    const float* X    = (const float*)d_in[0];
    const float* mask = (const float*)d_in[1];
    const float* Wq   = (const float*)d_in[2];
    const float* Wk   = (const float*)d_in[3];
    const float* Wv   = (const float*)d_in[4];
    const float* Wo   = (const float*)d_in[5];
    float* out = (float*)d_out;

    float *qb, *kb, *vb, *ab;
    cudaGetSymbolAddress((void**)&qb, g_q);
    cudaGetSymbolAddress((void**)&kb, g_k);
    cudaGetSymbolAddress((void**)&vb, g_v);
    cudaGetSymbolAddress((void**)&ab, g_attn);

    cudaFuncSetAttribute(attn_kernel,
                         cudaFuncAttributeMaxDynamicSharedMemorySize,
                         ATTN_SMEM_BYTES);

    dim3 gg(NHID / 128, MTOT / 128);   // 8 x 64
    gemm_xwt_kernel<<<gg, 256>>>(X, Wq, qb, 1);
    gemm_xwt_kernel<<<gg, 256>>>(X, Wk, kb, 1);
    gemm_xwt_kernel<<<gg, 256>>>(X, Wv, vb, 1);

    dim3 ga(NS / 128, NB * NHEADS);    // 16 x 64
    attn_kernel<<<ga, 256, ATTN_SMEM_BYTES>>>(mask);

    gemm_xwt_kernel<<<gg, 256>>>(ab, Wo, out, 0);
}

// round 3
// speedup vs baseline: 1.3750x; 1.3750x over previous
#include <cuda_runtime.h>
#include <cuda_bf16.h>
#include <cstdint>
#include <math.h>

#define NB 4
#define NS 2048
#define NHID 1024
#define NHEADS 16
#define DHEAD 64
#define MTOT (NB * NS)   // 8192

// Scratch (static device globals — no allocation APIs)
__device__ float g_q[NB * NHEADS * NS * DHEAD];
__device__ float g_k[NB * NHEADS * NS * DHEAD];
__device__ float g_v[NB * NHEADS * NS * DHEAD];
__device__ float g_attn[NB * NS * NHID];

// ===========================================================================
// Helpers
// ===========================================================================
__device__ __forceinline__ uint32_t smem_to_u32(const void* p) {
    uint32_t a;
    asm("{ .reg .u64 t; cvta.to.shared.u64 t, %1; cvt.u32.u64 %0, t; }"
        : "=r"(a) : "l"(p));
    return a;
}

__device__ __forceinline__ void ldmatrix_x4(uint32_t& d0, uint32_t& d1,
                                            uint32_t& d2, uint32_t& d3,
                                            uint32_t addr) {
    asm volatile("ldmatrix.sync.aligned.m8n8.x4.shared.b16 {%0,%1,%2,%3}, [%4];"
        : "=r"(d0), "=r"(d1), "=r"(d2), "=r"(d3) : "r"(addr));
}

__device__ __forceinline__ void mma_bf16(float* c, const uint32_t* a,
                                         const uint32_t* b) {
    asm volatile(
        "mma.sync.aligned.m16n8k16.row.col.f32.bf16.bf16.f32 "
        "{%0,%1,%2,%3}, {%4,%5,%6,%7}, {%8,%9}, {%0,%1,%2,%3};"
        : "+f"(c[0]), "+f"(c[1]), "+f"(c[2]), "+f"(c[3])
        : "r"(a[0]), "r"(a[1]), "r"(a[2]), "r"(a[3]), "r"(b[0]), "r"(b[1]));
}

// split fp32x4 -> bf16 hi/lo packed pairs (little-endian: .x holds cols c,c+1)
__device__ __forceinline__ void split4(float4 v, uint2& hi, uint2& lo) {
    __nv_bfloat16 h0 = __float2bfloat16_rn(v.x);
    __nv_bfloat16 h1 = __float2bfloat16_rn(v.y);
    __nv_bfloat16 h2 = __float2bfloat16_rn(v.z);
    __nv_bfloat16 h3 = __float2bfloat16_rn(v.w);
    __nv_bfloat16 l0 = __float2bfloat16_rn(v.x - __bfloat162float(h0));
    __nv_bfloat16 l1 = __float2bfloat16_rn(v.y - __bfloat162float(h1));
    __nv_bfloat16 l2 = __float2bfloat16_rn(v.z - __bfloat162float(h2));
    __nv_bfloat16 l3 = __float2bfloat16_rn(v.w - __bfloat162float(h3));
    __nv_bfloat162 p;
    p.x = h0; p.y = h1; hi.x = *reinterpret_cast<uint32_t*>(&p);
    p.x = h2; p.y = h3; hi.y = *reinterpret_cast<uint32_t*>(&p);
    p.x = l0; p.y = l1; lo.x = *reinterpret_cast<uint32_t*>(&p);
    p.x = l2; p.y = l3; lo.y = *reinterpret_cast<uint32_t*>(&p);
}

// ===========================================================================
// bf16-split tensor-core GEMM:  C[m,n] = sum_k A[m,k] * W[n,k]   (A @ W^T)
// A:[8192,1024]  W:[1024,1024]. CTA tile 128x128, K chunk 32, 8 warps (32x64).
// D = Ah*Bh + Ah*Bl + Al*Bh   (bf16 split, error ~2^-16)
// headMode=1: scatter into [B, NH, S, HD].
// ===========================================================================
#define BK 32
#define LDS_STRIDE 40                 // bf16 elements per row (32 + 8 pad)
#define TILE_B (128 * LDS_STRIDE * 2) // 10240 bytes per buffer

__global__ __launch_bounds__(256, 1)
void gemm_tc_kernel(const float* __restrict__ A, const float* __restrict__ W,
                    float* __restrict__ C, int headMode)
{
    __shared__ __align__(16) char smbuf[4 * TILE_B];  // Ah, Al, Bh, Bl
    const uint32_t sA_h = smem_to_u32(smbuf);
    const uint32_t sA_l = sA_h + TILE_B;
    const uint32_t sB_h = sA_h + 2 * TILE_B;
    const uint32_t sB_l = sA_h + 3 * TILE_B;

    const int t    = threadIdx.x;
    const int lane = t & 31;
    const int wid  = t >> 5;
    const int wm   = wid & 3;          // 4 M-warps (32 rows each)
    const int wn   = wid >> 2;         // 2 N-warps (64 cols each)
    const int m0   = blockIdx.y << 7;
    const int n0   = blockIdx.x << 7;

    // ---- global load mapping: each thread = half a row (16 floats) ----
    const int ldRow  = t >> 1;         // 0..127
    const int ldHalf = (t & 1) << 4;   // 0 or 16
    const float* Ap = A + (size_t)(m0 + ldRow) * NHID + ldHalf;
    const float* Wp = W + (size_t)(n0 + ldRow) * NHID + ldHalf;
    const uint32_t stsOff = (uint32_t)(ldRow * LDS_STRIDE + ldHalf) * 2;

    // ---- ldmatrix lane addressing ----
    const int rA = lane & 15;
    const int cA = (lane >> 4) << 3;
    const int rB = (lane & 7) + ((lane >> 4) << 3);
    const int cB = lane & 8;

    float acc[2][8][4];
#pragma unroll
    for (int mf = 0; mf < 2; mf++)
#pragma unroll
        for (int nf = 0; nf < 8; nf++)
#pragma unroll
            for (int r = 0; r < 4; r++) acc[mf][nf][r] = 0.f;

    // prologue: load chunk 0
    float4 ra[4], rb[4];
#pragma unroll
    for (int q = 0; q < 4; q++) {
        ra[q] = *(const float4*)(Ap + (q << 2));
        rb[q] = *(const float4*)(Wp + (q << 2));
    }

    for (int c = 0; c < NHID / BK; ++c) {
        __syncthreads();   // previous chunk's MMAs done reading smem

        // convert + store to smem
#pragma unroll
        for (int q = 0; q < 4; q++) {
            uint2 hi, lo;
            split4(ra[q], hi, lo);
            *(uint2*)(smbuf + (sA_h - smem_to_u32(smbuf)) + stsOff + (q << 3)) = hi; // placeholder
            // (see direct stores below)
        }
        // NOTE: do the stores via computed char* to keep ptxas happy
        {
            char* base = smbuf;
#pragma unroll
            for (int q = 0; q < 4; q++) {
                uint2 hi, lo;
                split4(ra[q], hi, lo);
                *(uint2*)(base + 0 * TILE_B + stsOff + (q << 3)) = hi;
                *(uint2*)(base + 1 * TILE_B + stsOff + (q << 3)) = lo;
                split4(rb[q], hi, lo);
                *(uint2*)(base + 2 * TILE_B + stsOff + (q << 3)) = hi;
                *(uint2*)(base + 3 * TILE_B + stsOff + (q << 3)) = lo;
            }
        }
        __syncthreads();

        // prefetch next chunk (latency hidden under MMAs)
        if (c + 1 < NHID / BK) {
            const int k1 = (c + 1) << 5;
#pragma unroll
            for (int q = 0; q < 4; q++) {
                ra[q] = *(const float4*)(Ap + k1 + (q << 2));
                rb[q] = *(const float4*)(Wp + k1 + (q << 2));
            }
        }

        // ---- MMA over the 32-wide chunk (two k16 steps) ----
#pragma unroll
        for (int ks = 0; ks < 2; ks++) {
            const int k0 = ks << 4;
            uint32_t ah[2][4], al[2][4], bh[8][2], bl[8][2];
#pragma unroll
            for (int mf = 0; mf < 2; mf++) {
                uint32_t rowOff =
                    (uint32_t)((wm * 32 + mf * 16 + rA) * LDS_STRIDE + k0 + cA) * 2;
                ldmatrix_x4(ah[mf][0], ah[mf][1], ah[mf][2], ah[mf][3], sA_h + rowOff);
                ldmatrix_x4(al[mf][0], al[mf][1], al[mf][2], al[mf][3], sA_l + rowOff);
            }
#pragma unroll
            for (int p = 0; p < 4; p++) {
                uint32_t rowOff =
                    (uint32_t)((wn * 64 + p * 16 + rB) * LDS_STRIDE + k0 + cB) * 2;
                uint32_t d0, d1, d2, d3;
                ldmatrix_x4(d0, d1, d2, d3, sB_h + rowOff);
                bh[2 * p][0] = d0; bh[2 * p][1] = d1;
                bh[2 * p + 1][0] = d2; bh[2 * p + 1][1] = d3;
                ldmatrix_x4(d0, d1, d2, d3, sB_l + rowOff);
                bl[2 * p][0] = d0; bl[2 * p][1] = d1;
                bl[2 * p + 1][0] = d2; bl[2 * p + 1][1] = d3;
            }
#pragma unroll
            for (int mf = 0; mf < 2; mf++)
#pragma unroll
                for (int nf = 0; nf < 8; nf++) {
                    mma_bf16(acc[mf][nf], ah[mf], bh[nf]);
                    mma_bf16(acc[mf][nf], ah[mf], bl[nf]);
                    mma_bf16(acc[mf][nf], al[mf], bh[nf]);
                }
        }
    }

    // ---- epilogue ----
    const int rowBase = m0 + wm * 32 + (lane >> 2);
    const int colBase = n0 + wn * 64 + (lane & 3) * 2;
#pragma unroll
    for (int mf = 0; mf < 2; mf++) {
#pragma unroll
        for (int nf = 0; nf < 8; nf++) {
            int mA = rowBase + mf * 16;
            int n  = colBase + nf * 8;
            if (headMode) {
                int h = n >> 6, d = n & 63;
#pragma unroll
                for (int half = 0; half < 2; half++) {
                    int m = mA + half * 8;
                    int b = m >> 11, s = m & (NS - 1);
                    float2 v = make_float2(acc[mf][nf][half * 2],
                                           acc[mf][nf][half * 2 + 1]);
                    *(float2*)(C + ((((size_t)(b * NHEADS + h)) * NS + s) << 6) + d) = v;
                }
            } else {
#pragma unroll
                for (int half = 0; half < 2; half++) {
                    int m = mA + half * 8;
                    float2 v = make_float2(acc[mf][nf][half * 2],
                                           acc[mf][nf][half * 2 + 1]);
                    *(float2*)(C + (size_t)m * NHID + n) = v;
                }
            }
        }
    }
}

// ---------------------------------------------------------------------------
// Flash attention (SIMT fp32, unchanged): one CTA = (b,h) x 128 q-rows
// ---------------------------------------------------------------------------
#define QROWS 128
#define KROWS 64
#define LDP 68

#define ATTN_SMEM_FLOATS (QROWS*LDP + KROWS*LDP + KROWS*LDP + QROWS*LDP + 64)
#define ATTN_SMEM_BYTES  (ATTN_SMEM_FLOATS * 4)

__global__ __launch_bounds__(256)
void attn_kernel(const float* __restrict__ mask)
{
    extern __shared__ float smf[];
    float* Qs  = smf;
    float* Ks  = Qs + QROWS * LDP;
    float* Vt  = Ks + KROWS * LDP;
    float* Ps  = Vt + KROWS * LDP;
    float* msk = Ps + QROWS * LDP;

    const int t  = threadIdx.x;
    const int tx = t & 15;
    const int ty = t >> 4;

    const int bh = blockIdx.y;
    const int b  = bh >> 4;
    const int q0 = blockIdx.x << 7;
    const int h  = bh & 15;

    const float* qp = g_q + ((size_t)bh * NS + q0) * DHEAD;
    const float* kp = g_k + (size_t)bh * NS * DHEAD;
    const float* vp = g_v + (size_t)bh * NS * DHEAD;

    for (int i = t; i < QROWS * 16; i += 256) {
        int r  = i >> 4;
        int c4 = (i & 15) << 2;
        float4 v = *(const float4*)&qp[r * DHEAD + c4];
        Qs[r * LDP + c4 + 0] = v.x; Qs[r * LDP + c4 + 1] = v.y;
        Qs[r * LDP + c4 + 2] = v.z; Qs[r * LDP + c4 + 3] = v.w;
    }

    float mrow[8], lrow[8], o[8][4];
#pragma unroll
    for (int i = 0; i < 8; i++) {
        mrow[i] = -INFINITY;
        lrow[i] = 0.f;
#pragma unroll
        for (int j = 0; j < 4; j++) o[i][j] = 0.f;
    }

    const float scaling = 0.125f;

    for (int kt = 0; kt < NS; kt += KROWS) {
        __syncthreads();
        for (int i = t; i < KROWS * 16; i += 256) {
            int r  = i >> 4;
            int c4 = (i & 15) << 2;
            float4 kv = *(const float4*)&kp[(kt + r) * DHEAD + c4];
            Ks[r * LDP + c4 + 0] = kv.x; Ks[r * LDP + c4 + 1] = kv.y;
            Ks[r * LDP + c4 + 2] = kv.z; Ks[r * LDP + c4 + 3] = kv.w;
            float4 vv = *(const float4*)&vp[(kt + r) * DHEAD + c4];
            Vt[(c4 + 0) * LDP + r] = vv.x; Vt[(c4 + 1) * LDP + r] = vv.y;
            Vt[(c4 + 2) * LDP + r] = vv.z; Vt[(c4 + 3) * LDP + r] = vv.w;
        }
        if (t < KROWS) msk[t] = mask[b * NS + kt + t];
        __syncthreads();

        float s[8][4];
#pragma unroll
        for (int i = 0; i < 8; i++)
#pragma unroll
            for (int j = 0; j < 4; j++) s[i][j] = 0.f;

#pragma unroll
        for (int d4 = 0; d4 < DHEAD; d4 += 4) {
            float4 q4[8], k4[4];
#pragma unroll
            for (int i = 0; i < 8; i++)
                q4[i] = *(const float4*)&Qs[(ty + (i << 4)) * LDP + d4];
#pragma unroll
            for (int j = 0; j < 4; j++)
                k4[j] = *(const float4*)&Ks[(tx + (j << 4)) * LDP + d4];
#pragma unroll
            for (int i = 0; i < 8; i++)
#pragma unroll
                for (int j = 0; j < 4; j++) {
                    s[i][j] = fmaf(q4[i].x, k4[j].x, s[i][j]);
                    s[i][j] = fmaf(q4[i].y, k4[j].y, s[i][j]);
                    s[i][j] = fmaf(q4[i].z, k4[j].z, s[i][j]);
                    s[i][j] = fmaf(q4[i].w, k4[j].w, s[i][j]);
                }
        }

#pragma unroll
        for (int i = 0; i < 8; i++)
#pragma unroll
            for (int j = 0; j < 4; j++)
                s[i][j] = fmaf(s[i][j], scaling, msk[tx + (j << 4)]);

        float tmax[8];
#pragma unroll
        for (int i = 0; i < 8; i++) {
            float m01 = fmaxf(s[i][0], s[i][1]);
            float m23 = fmaxf(s[i][2], s[i][3]);
            tmax[i] = fmaxf(m01, m23);
        }
#pragma unroll
        for (int off = 8; off >= 1; off >>= 1)
#pragma unroll
            for (int i = 0; i < 8; i++)
                tmax[i] = fmaxf(tmax[i], __shfl_xor_sync(0xffffffffu, tmax[i], off));

        float rs[8];
#pragma unroll
        for (int i = 0; i < 8; i++) {
            float mnew = fmaxf(mrow[i], tmax[i]);
            float corr = __expf(mrow[i] - mnew);
            mrow[i] = mnew;
            float r = 0.f;
#pragma unroll
            for (int j = 0; j < 4; j++) {
                float p = __expf(s[i][j] - mnew);
                r += p;
                Ps[(ty + (i << 4)) * LDP + tx + (j << 4)] = p;
            }
            rs[i] = r;
            lrow[i] = lrow[i] * corr;
#pragma unroll
            for (int j = 0; j < 4; j++) o[i][j] *= corr;
        }
#pragma unroll
        for (int off = 8; off >= 1; off >>= 1)
#pragma unroll
            for (int i = 0; i < 8; i++)
                rs[i] += __shfl_xor_sync(0xffffffffu, rs[i], off);
#pragma unroll
        for (int i = 0; i < 8; i++) lrow[i] += rs[i];

        __syncthreads();

#pragma unroll
        for (int k4 = 0; k4 < KROWS; k4 += 4) {
            float4 p4[8], v4[4];
#pragma unroll
            for (int i = 0; i < 8; i++)
                p4[i] = *(const float4*)&Ps[(ty + (i << 4)) * LDP + k4];
#pragma unroll
            for (int j = 0; j < 4; j++)
                v4[j] = *(const float4*)&Vt[(tx + (j << 4)) * LDP + k4];
#pragma unroll
            for (int i = 0; i < 8; i++)
#pragma unroll
                for (int j = 0; j < 4; j++) {
                    o[i][j] = fmaf(p4[i].x, v4[j].x, o[i][j]);
                    o[i][j] = fmaf(p4[i].y, v4[j].y, o[i][j]);
                    o[i][j] = fmaf(p4[i].z, v4[j].z, o[i][j]);
                    o[i][j] = fmaf(p4[i].w, v4[j].w, o[i][j]);
                }
        }
    }

#pragma unroll
    for (int i = 0; i < 8; i++) {
        float inv = 1.f / lrow[i];
        int m = q0 + ty + (i << 4);
        size_t base = ((size_t)(b * NS) + m) * NHID + h * DHEAD;
#pragma unroll
        for (int j = 0; j < 4; j++) {
            int d = tx + (j << 4);
            g_attn[base + d] = o[i][j] * inv;
        }
    }
}

// ---------------------------------------------------------------------------
// Launch
// ---------------------------------------------------------------------------
extern "C" void kernel_launch(void* const* d_in, const int* in_sizes, int n_in,
                              void* d_out, int out_size)
{
    const float* X    = (const float*)d_in[0];
    const float* mask = (const float*)d_in[1];
    const float* Wq   = (const float*)d_in[2];
    const float* Wk   = (const float*)d_in[3];
    const float* Wv   = (const float*)d_in[4];
    const float* Wo   = (const float*)d_in[5];
    float* out = (float*)d_out;

    float *qb, *kb, *vb, *ab;
    cudaGetSymbolAddress((void**)&qb, g_q);
    cudaGetSymbolAddress((void**)&kb, g_k);
    cudaGetSymbolAddress((void**)&vb, g_v);
    cudaGetSymbolAddress((void**)&ab, g_attn);

    cudaFuncSetAttribute(attn_kernel,
                         cudaFuncAttributeMaxDynamicSharedMemorySize, ATTN_SMEM_BYTES);

    dim3 gg(NHID / 128, MTOT / 128);   // 8 x 64
    gemm_tc_kernel<<<gg, 256>>>(X, Wq, qb, 1);
    gemm_tc_kernel<<<gg, 256>>>(X, Wk, kb, 1);
    gemm_tc_kernel<<<gg, 256>>>(X, Wv, vb, 1);

    dim3 ga(NS / 128, NB * NHEADS);    // 16 x 64
    attn_kernel<<<ga, 256, ATTN_SMEM_BYTES>>>(mask);

    gemm_tc_kernel<<<gg, 256>>>(ab, Wo, out, 0);
}

// round 4
// speedup vs baseline: 2.2704x; 1.6513x over previous
#include <cuda_runtime.h>
#include <cuda_bf16.h>
#include <cstdint>
#include <math.h>

#define NB 4
#define NS 2048
#define NHID 1024
#define NHEADS 16
#define DHEAD 64
#define MTOT (NB * NS)   // 8192

// Scratch (static device globals — no allocation APIs)
__device__ float g_q[NB * NHEADS * NS * DHEAD];
__device__ float g_k[NB * NHEADS * NS * DHEAD];
__device__ float g_v[NB * NHEADS * NS * DHEAD];
__device__ float g_attn[NB * NS * NHID];

// ===========================================================================
// Helpers
// ===========================================================================
__device__ __forceinline__ uint32_t smem_to_u32(const void* p) {
    uint32_t a;
    asm("{ .reg .u64 t; cvta.to.shared.u64 t, %1; cvt.u32.u64 %0, t; }"
        : "=r"(a) : "l"(p));
    return a;
}

__device__ __forceinline__ void ldmatrix_x4(uint32_t& d0, uint32_t& d1,
                                            uint32_t& d2, uint32_t& d3,
                                            uint32_t addr) {
    asm volatile("ldmatrix.sync.aligned.m8n8.x4.shared.b16 {%0,%1,%2,%3}, [%4];"
        : "=r"(d0), "=r"(d1), "=r"(d2), "=r"(d3) : "r"(addr));
}

__device__ __forceinline__ void ldmatrix_x4_trans(uint32_t& d0, uint32_t& d1,
                                                  uint32_t& d2, uint32_t& d3,
                                                  uint32_t addr) {
    asm volatile("ldmatrix.sync.aligned.m8n8.x4.trans.shared.b16 {%0,%1,%2,%3}, [%4];"
        : "=r"(d0), "=r"(d1), "=r"(d2), "=r"(d3) : "r"(addr));
}

__device__ __forceinline__ void mma_bf16(float* c, const uint32_t* a,
                                         const uint32_t* b) {
    asm volatile(
        "mma.sync.aligned.m16n8k16.row.col.f32.bf16.bf16.f32 "
        "{%0,%1,%2,%3}, {%4,%5,%6,%7}, {%8,%9}, {%0,%1,%2,%3};"
        : "+f"(c[0]), "+f"(c[1]), "+f"(c[2]), "+f"(c[3])
        : "r"(a[0]), "r"(a[1]), "r"(a[2]), "r"(a[3]), "r"(b[0]), "r"(b[1]));
}

__device__ __forceinline__ uint32_t packbf(__nv_bfloat16 x, __nv_bfloat16 y) {
    __nv_bfloat162 p; p.x = x; p.y = y;
    return *reinterpret_cast<uint32_t*>(&p);
}

// split fp32 pair -> bf16 hi/lo packed
__device__ __forceinline__ void split2(float x, float y,
                                       uint32_t& hi, uint32_t& lo) {
    __nv_bfloat16 hx = __float2bfloat16_rn(x);
    __nv_bfloat16 hy = __float2bfloat16_rn(y);
    hi = packbf(hx, hy);
    lo = packbf(__float2bfloat16_rn(x - __bfloat162float(hx)),
                __float2bfloat16_rn(y - __bfloat162float(hy)));
}

// split fp32x4 -> bf16 hi/lo packed pairs
__device__ __forceinline__ void split4(float4 v, uint2& hi, uint2& lo) {
    split2(v.x, v.y, hi.x, lo.x);
    split2(v.z, v.w, hi.y, lo.y);
}

// ===========================================================================
// bf16-split tensor-core GEMM:  C[m,n] = sum_k A[m,k] * W[n,k]   (A @ W^T)
// CTA tile 128x128, K chunk 32, 8 warps (32x64 each).
// D = Ah*Bh + Ah*Bl + Al*Bh
// ===========================================================================
#define BK 32
#define LDS_STRIDE 40                 // bf16 elements per row (32 + 8 pad)
#define TILE_B (128 * LDS_STRIDE * 2) // 10240 bytes per buffer

__global__ __launch_bounds__(256, 1)
void gemm_tc_kernel(const float* __restrict__ A, const float* __restrict__ W,
                    float* __restrict__ C, int headMode)
{
    __shared__ __align__(16) char smbuf[4 * TILE_B];  // Ah, Al, Bh, Bl
    const uint32_t sA_h = smem_to_u32(smbuf);
    const uint32_t sA_l = sA_h + TILE_B;
    const uint32_t sB_h = sA_h + 2 * TILE_B;
    const uint32_t sB_l = sA_h + 3 * TILE_B;

    const int t    = threadIdx.x;
    const int lane = t & 31;
    const int wid  = t >> 5;
    const int wm   = wid & 3;
    const int wn   = wid >> 2;
    const int m0   = blockIdx.y << 7;
    const int n0   = blockIdx.x << 7;

    const int ldRow  = t >> 1;
    const int ldHalf = (t & 1) << 4;
    const float* Ap = A + (size_t)(m0 + ldRow) * NHID + ldHalf;
    const float* Wp = W + (size_t)(n0 + ldRow) * NHID + ldHalf;
    const uint32_t stsOff = (uint32_t)(ldRow * LDS_STRIDE + ldHalf) * 2;

    const int rA = lane & 15;
    const int cA = (lane >> 4) << 3;
    const int rB = (lane & 7) + ((lane >> 4) << 3);
    const int cB = lane & 8;

    float acc[2][8][4];
#pragma unroll
    for (int mf = 0; mf < 2; mf++)
#pragma unroll
        for (int nf = 0; nf < 8; nf++)
#pragma unroll
            for (int r = 0; r < 4; r++) acc[mf][nf][r] = 0.f;

    float4 ra[4], rb[4];
#pragma unroll
    for (int q = 0; q < 4; q++) {
        ra[q] = *(const float4*)(Ap + (q << 2));
        rb[q] = *(const float4*)(Wp + (q << 2));
    }

    for (int c = 0; c < NHID / BK; ++c) {
        __syncthreads();
        {
            char* base = smbuf;
#pragma unroll
            for (int q = 0; q < 4; q++) {
                uint2 hi, lo;
                split4(ra[q], hi, lo);
                *(uint2*)(base + 0 * TILE_B + stsOff + (q << 3)) = hi;
                *(uint2*)(base + 1 * TILE_B + stsOff + (q << 3)) = lo;
                split4(rb[q], hi, lo);
                *(uint2*)(base + 2 * TILE_B + stsOff + (q << 3)) = hi;
                *(uint2*)(base + 3 * TILE_B + stsOff + (q << 3)) = lo;
            }
        }
        __syncthreads();

        if (c + 1 < NHID / BK) {
            const int k1 = (c + 1) << 5;
#pragma unroll
            for (int q = 0; q < 4; q++) {
                ra[q] = *(const float4*)(Ap + k1 + (q << 2));
                rb[q] = *(const float4*)(Wp + k1 + (q << 2));
            }
        }

#pragma unroll
        for (int ks = 0; ks < 2; ks++) {
            const int k0 = ks << 4;
            uint32_t ah[2][4], al[2][4], bh[8][2], bl[8][2];
#pragma unroll
            for (int mf = 0; mf < 2; mf++) {
                uint32_t rowOff =
                    (uint32_t)((wm * 32 + mf * 16 + rA) * LDS_STRIDE + k0 + cA) * 2;
                ldmatrix_x4(ah[mf][0], ah[mf][1], ah[mf][2], ah[mf][3], sA_h + rowOff);
                ldmatrix_x4(al[mf][0], al[mf][1], al[mf][2], al[mf][3], sA_l + rowOff);
            }
#pragma unroll
            for (int p = 0; p < 4; p++) {
                uint32_t rowOff =
                    (uint32_t)((wn * 64 + p * 16 + rB) * LDS_STRIDE + k0 + cB) * 2;
                uint32_t d0, d1, d2, d3;
                ldmatrix_x4(d0, d1, d2, d3, sB_h + rowOff);
                bh[2 * p][0] = d0; bh[2 * p][1] = d1;
                bh[2 * p + 1][0] = d2; bh[2 * p + 1][1] = d3;
                ldmatrix_x4(d0, d1, d2, d3, sB_l + rowOff);
                bl[2 * p][0] = d0; bl[2 * p][1] = d1;
                bl[2 * p + 1][0] = d2; bl[2 * p + 1][1] = d3;
            }
#pragma unroll
            for (int mf = 0; mf < 2; mf++)
#pragma unroll
                for (int nf = 0; nf < 8; nf++) {
                    mma_bf16(acc[mf][nf], ah[mf], bh[nf]);
                    mma_bf16(acc[mf][nf], ah[mf], bl[nf]);
                    mma_bf16(acc[mf][nf], al[mf], bh[nf]);
                }
        }
    }

    const int rowBase = m0 + wm * 32 + (lane >> 2);
    const int colBase = n0 + wn * 64 + (lane & 3) * 2;
#pragma unroll
    for (int mf = 0; mf < 2; mf++) {
#pragma unroll
        for (int nf = 0; nf < 8; nf++) {
            int mA = rowBase + mf * 16;
            int n  = colBase + nf * 8;
            if (headMode) {
                int h = n >> 6, d = n & 63;
#pragma unroll
                for (int half = 0; half < 2; half++) {
                    int m = mA + half * 8;
                    int b = m >> 11, s = m & (NS - 1);
                    float2 v = make_float2(acc[mf][nf][half * 2],
                                           acc[mf][nf][half * 2 + 1]);
                    *(float2*)(C + ((((size_t)(b * NHEADS + h)) * NS + s) << 6) + d) = v;
                }
            } else {
#pragma unroll
                for (int half = 0; half < 2; half++) {
                    int m = mA + half * 8;
                    float2 v = make_float2(acc[mf][nf][half * 2],
                                           acc[mf][nf][half * 2 + 1]);
                    *(float2*)(C + (size_t)m * NHID + n) = v;
                }
            }
        }
    }
}

// ===========================================================================
// Tensor-core flash attention (bf16 split): one CTA = (b,h) x 128 q-rows.
// 8 warps, warp w owns rows 16w..16w+15. K-tile = 128.
// QK^T: 3-term split; P and V: 3-term split. fp32 accumulate throughout.
// ===========================================================================
#define KT 128
#define ALDS 72            // bf16 elems per smem row (64 + 8 pad)
#define QTB (128 * ALDS * 2)   // 18432 bytes per tile buffer

// smem byte offsets
#define OFF_QH 0
#define OFF_QL (1 * QTB)
#define OFF_KH (2 * QTB)
#define OFF_KL (3 * QTB)
#define OFF_VH (4 * QTB)
#define OFF_VL (5 * QTB)
#define OFF_MSK (6 * QTB)
#define ATTN_SMEM (OFF_MSK + KT * 4)

__global__ __launch_bounds__(256, 1)
void attn_tc_kernel(const float* __restrict__ mask)
{
    extern __shared__ char smc[];
    const uint32_t sbase = smem_to_u32(smc);
    float* msk = (float*)(smc + OFF_MSK);

    const int t    = threadIdx.x;
    const int lane = t & 31;
    const int w    = t >> 5;

    const int bh = blockIdx.y;
    const int b  = bh >> 4;
    const int h  = bh & 15;
    const int q0 = blockIdx.x << 7;

    const int rA = lane & 15;
    const int cA = (lane >> 4) << 3;
    const int rB = (lane & 7) + ((lane >> 4) << 3);
    const int cB = lane & 8;
    const int c0 = (lane & 3) << 1;

    // ---- load Q tile (128x64 fp32), split to bf16 hi/lo in smem ----
    const float* qp = g_q + ((size_t)bh * NS + q0) * DHEAD;
    {
        int row  = t >> 1;
        int colb = (t & 1) << 5;
        uint32_t off = (uint32_t)(row * ALDS + colb) * 2;
#pragma unroll
        for (int qd = 0; qd < 8; qd++) {
            uint2 hi, lo;
            split4(*(const float4*)(qp + row * DHEAD + colb + qd * 4), hi, lo);
            *(uint2*)(smc + OFF_QH + off + qd * 8) = hi;
            *(uint2*)(smc + OFF_QL + off + qd * 8) = lo;
        }
    }

    float accs[16][4];
    float acco[8][4];
    float m0 = -INFINITY, m1 = -INFINITY, l0 = 0.f, l1 = 0.f;
#pragma unroll
    for (int nf = 0; nf < 8; nf++)
#pragma unroll
        for (int r = 0; r < 4; r++) acco[nf][r] = 0.f;

    const float* kp = g_k + (size_t)bh * NS * DHEAD;
    const float* vp = g_v + (size_t)bh * NS * DHEAD;

    for (int kt = 0; kt < NS / KT; kt++) {
        __syncthreads();   // previous tile's MMAs done with K/V smem (and Q stores on iter 0)

        // ---- load K/V tile (128x64 fp32 each), split to smem ----
        {
            int row  = t >> 1;
            int colb = (t & 1) << 5;
            const float* kr = kp + (size_t)(kt * KT + row) * DHEAD + colb;
            const float* vr = vp + (size_t)(kt * KT + row) * DHEAD + colb;
            uint32_t off = (uint32_t)(row * ALDS + colb) * 2;
#pragma unroll
            for (int qd = 0; qd < 8; qd++) {
                uint2 hi, lo;
                split4(*(const float4*)(kr + qd * 4), hi, lo);
                *(uint2*)(smc + OFF_KH + off + qd * 8) = hi;
                *(uint2*)(smc + OFF_KL + off + qd * 8) = lo;
                split4(*(const float4*)(vr + qd * 4), hi, lo);
                *(uint2*)(smc + OFF_VH + off + qd * 8) = hi;
                *(uint2*)(smc + OFF_VL + off + qd * 8) = lo;
            }
        }
        if (t < KT) msk[t] = mask[b * NS + kt * KT + t];
        __syncthreads();

        // ---- S = Q K^T (16 rows x 128 cols per warp) ----
#pragma unroll
        for (int nf = 0; nf < 16; nf++)
#pragma unroll
            for (int r = 0; r < 4; r++) accs[nf][r] = 0.f;

#pragma unroll
        for (int ks = 0; ks < 4; ks++) {
            uint32_t aqh[4], aql[4];
            uint32_t qoff = (uint32_t)((w * 16 + rA) * ALDS + ks * 16 + cA) * 2;
            ldmatrix_x4(aqh[0], aqh[1], aqh[2], aqh[3], sbase + OFF_QH + qoff);
            ldmatrix_x4(aql[0], aql[1], aql[2], aql[3], sbase + OFF_QL + qoff);
#pragma unroll
            for (int p = 0; p < 8; p++) {
                uint32_t koff = (uint32_t)((p * 16 + rB) * ALDS + ks * 16 + cB) * 2;
                uint32_t h0, h1, h2, h3, e0, e1, e2, e3;
                ldmatrix_x4(h0, h1, h2, h3, sbase + OFF_KH + koff);
                ldmatrix_x4(e0, e1, e2, e3, sbase + OFF_KL + koff);
                uint32_t bhi0[2] = {h0, h1}, bhi1[2] = {h2, h3};
                uint32_t blo0[2] = {e0, e1}, blo1[2] = {e2, e3};
                mma_bf16(accs[2 * p],     aqh, bhi0);
                mma_bf16(accs[2 * p],     aqh, blo0);
                mma_bf16(accs[2 * p],     aql, bhi0);
                mma_bf16(accs[2 * p + 1], aqh, bhi1);
                mma_bf16(accs[2 * p + 1], aqh, blo1);
                mma_bf16(accs[2 * p + 1], aql, bhi1);
            }
        }

        // ---- scale + mask ----
#pragma unroll
        for (int nf = 0; nf < 16; nf++) {
            float mk0 = msk[nf * 8 + c0];
            float mk1 = msk[nf * 8 + c0 + 1];
            accs[nf][0] = fmaf(accs[nf][0], 0.125f, mk0);
            accs[nf][1] = fmaf(accs[nf][1], 0.125f, mk1);
            accs[nf][2] = fmaf(accs[nf][2], 0.125f, mk0);
            accs[nf][3] = fmaf(accs[nf][3], 0.125f, mk1);
        }

        // ---- online softmax (rows gr and gr+8) ----
        float tm0 = -INFINITY, tm1 = -INFINITY;
#pragma unroll
        for (int nf = 0; nf < 16; nf++) {
            tm0 = fmaxf(tm0, fmaxf(accs[nf][0], accs[nf][1]));
            tm1 = fmaxf(tm1, fmaxf(accs[nf][2], accs[nf][3]));
        }
        tm0 = fmaxf(tm0, __shfl_xor_sync(0xffffffffu, tm0, 1));
        tm0 = fmaxf(tm0, __shfl_xor_sync(0xffffffffu, tm0, 2));
        tm1 = fmaxf(tm1, __shfl_xor_sync(0xffffffffu, tm1, 1));
        tm1 = fmaxf(tm1, __shfl_xor_sync(0xffffffffu, tm1, 2));

        float mn0 = fmaxf(m0, tm0), mn1 = fmaxf(m1, tm1);
        float cr0 = __expf(m0 - mn0), cr1 = __expf(m1 - mn1);
        m0 = mn0; m1 = mn1;

        float rs0 = 0.f, rs1 = 0.f;
#pragma unroll
        for (int nf = 0; nf < 16; nf++) {
            accs[nf][0] = __expf(accs[nf][0] - mn0);
            accs[nf][1] = __expf(accs[nf][1] - mn0);
            accs[nf][2] = __expf(accs[nf][2] - mn1);
            accs[nf][3] = __expf(accs[nf][3] - mn1);
            rs0 += accs[nf][0] + accs[nf][1];
            rs1 += accs[nf][2] + accs[nf][3];
        }
        rs0 += __shfl_xor_sync(0xffffffffu, rs0, 1);
        rs0 += __shfl_xor_sync(0xffffffffu, rs0, 2);
        rs1 += __shfl_xor_sync(0xffffffffu, rs1, 1);
        rs1 += __shfl_xor_sync(0xffffffffu, rs1, 2);
        l0 = l0 * cr0 + rs0;
        l1 = l1 * cr1 + rs1;

#pragma unroll
        for (int nf = 0; nf < 8; nf++) {
            acco[nf][0] *= cr0; acco[nf][1] *= cr0;
            acco[nf][2] *= cr1; acco[nf][3] *= cr1;
        }

        // ---- O += P V  (P fragments built in registers) ----
#pragma unroll
        for (int kc = 0; kc < 8; kc++) {
            uint32_t aph[4], apl[4];
            split2(accs[2 * kc][0],     accs[2 * kc][1],     aph[0], apl[0]);
            split2(accs[2 * kc][2],     accs[2 * kc][3],     aph[1], apl[1]);
            split2(accs[2 * kc + 1][0], accs[2 * kc + 1][1], aph[2], apl[2]);
            split2(accs[2 * kc + 1][2], accs[2 * kc + 1][3], aph[3], apl[3]);
#pragma unroll
            for (int pv = 0; pv < 4; pv++) {
                uint32_t voff = (uint32_t)((kc * 16 + rA) * ALDS + pv * 16 + cA) * 2;
                uint32_t h0, h1, h2, h3, e0, e1, e2, e3;
                ldmatrix_x4_trans(h0, h1, h2, h3, sbase + OFF_VH + voff);
                ldmatrix_x4_trans(e0, e1, e2, e3, sbase + OFF_VL + voff);
                uint32_t bvh0[2] = {h0, h1}, bvh1[2] = {h2, h3};
                uint32_t bvl0[2] = {e0, e1}, bvl1[2] = {e2, e3};
                mma_bf16(acco[2 * pv],     aph, bvh0);
                mma_bf16(acco[2 * pv],     aph, bvl0);
                mma_bf16(acco[2 * pv],     apl, bvh0);
                mma_bf16(acco[2 * pv + 1], aph, bvh1);
                mma_bf16(acco[2 * pv + 1], aph, bvl1);
                mma_bf16(acco[2 * pv + 1], apl, bvh1);
            }
        }
    }

    // ---- epilogue: normalize, write [B,S,H] ----
    float inv0 = 1.f / l0;
    float inv1 = 1.f / l1;
    int row0 = q0 + w * 16 + (lane >> 2);
#pragma unroll
    for (int nf = 0; nf < 8; nf++) {
        int d = nf * 8 + c0;
        size_t base0 = ((size_t)(b * NS) + row0) * NHID + h * DHEAD + d;
        *(float2*)(g_attn + base0) =
            make_float2(acco[nf][0] * inv0, acco[nf][1] * inv0);
        *(float2*)(g_attn + base0 + (size_t)8 * NHID) =
            make_float2(acco[nf][2] * inv1, acco[nf][3] * inv1);
    }
}

// ---------------------------------------------------------------------------
// Launch
// ---------------------------------------------------------------------------
extern "C" void kernel_launch(void* const* d_in, const int* in_sizes, int n_in,
                              void* d_out, int out_size)
{
    const float* X    = (const float*)d_in[0];
    const float* mask = (const float*)d_in[1];
    const float* Wq   = (const float*)d_in[2];
    const float* Wk   = (const float*)d_in[3];
    const float* Wv   = (const float*)d_in[4];
    const float* Wo   = (const float*)d_in[5];
    float* out = (float*)d_out;

    float *qb, *kb, *vb, *ab;
    cudaGetSymbolAddress((void**)&qb, g_q);
    cudaGetSymbolAddress((void**)&kb, g_k);
    cudaGetSymbolAddress((void**)&vb, g_v);
    cudaGetSymbolAddress((void**)&ab, g_attn);

    cudaFuncSetAttribute(attn_tc_kernel,
                         cudaFuncAttributeMaxDynamicSharedMemorySize, ATTN_SMEM);

    dim3 gg(NHID / 128, MTOT / 128);   // 8 x 64
    gemm_tc_kernel<<<gg, 256>>>(X, Wq, qb, 1);
    gemm_tc_kernel<<<gg, 256>>>(X, Wk, kb, 1);
    gemm_tc_kernel<<<gg, 256>>>(X, Wv, vb, 1);

    dim3 ga(NS / 128, NB * NHEADS);    // 16 x 64
    attn_tc_kernel<<<ga, 256, ATTN_SMEM>>>(mask);

    gemm_tc_kernel<<<gg, 256>>>(ab, Wo, out, 0);
}

// round 5
// speedup vs baseline: 3.0606x; 1.3480x over previous
#include <cuda_runtime.h>
#include <cuda_bf16.h>
#include <cstdint>
#include <math.h>

#define NB 4
#define NS 2048
#define NHID 1024
#define NHEADS 16
#define DHEAD 64
#define MTOT (NB * NS)   // 8192

// ---------------------------------------------------------------------------
// Global scratch (bf16 hi/lo pairs everywhere)
// ---------------------------------------------------------------------------
__device__ __nv_bfloat16 g_xh[MTOT * NHID], g_xl[MTOT * NHID];
__device__ __nv_bfloat16 g_wqh[NHID * NHID], g_wql[NHID * NHID];
__device__ __nv_bfloat16 g_wkh[NHID * NHID], g_wkl[NHID * NHID];
__device__ __nv_bfloat16 g_wvh[NHID * NHID], g_wvl[NHID * NHID];
__device__ __nv_bfloat16 g_woh[NHID * NHID], g_wol[NHID * NHID];
__device__ __nv_bfloat16 g_qh[NB * NHEADS * NS * DHEAD], g_ql[NB * NHEADS * NS * DHEAD];
__device__ __nv_bfloat16 g_kh[NB * NHEADS * NS * DHEAD], g_kl[NB * NHEADS * NS * DHEAD];
__device__ __nv_bfloat16 g_vh[NB * NHEADS * NS * DHEAD], g_vl[NB * NHEADS * NS * DHEAD];
__device__ __nv_bfloat16 g_ah[MTOT * NHID], g_al[MTOT * NHID];

// ===========================================================================
// Helpers
// ===========================================================================
__device__ __forceinline__ uint32_t smem_to_u32(const void* p) {
    uint32_t a;
    asm("{ .reg .u64 t; cvta.to.shared.u64 t, %1; cvt.u32.u64 %0, t; }"
        : "=r"(a) : "l"(p));
    return a;
}

__device__ __forceinline__ void cp_async16(uint32_t s, const void* g) {
    asm volatile("cp.async.cg.shared.global [%0], [%1], 16;" :: "r"(s), "l"(g));
}
__device__ __forceinline__ void cp_async8(uint32_t s, const void* g) {
    asm volatile("cp.async.ca.shared.global [%0], [%1], 8;" :: "r"(s), "l"(g));
}
__device__ __forceinline__ void cp_commit() {
    asm volatile("cp.async.commit_group;" ::: "memory");
}
template <int N>
__device__ __forceinline__ void cp_wait() {
    asm volatile("cp.async.wait_group %0;" :: "n"(N) : "memory");
}

__device__ __forceinline__ void ldmatrix_x4(uint32_t& d0, uint32_t& d1,
                                            uint32_t& d2, uint32_t& d3,
                                            uint32_t addr) {
    asm volatile("ldmatrix.sync.aligned.m8n8.x4.shared.b16 {%0,%1,%2,%3}, [%4];"
        : "=r"(d0), "=r"(d1), "=r"(d2), "=r"(d3) : "r"(addr));
}
__device__ __forceinline__ void ldmatrix_x4_trans(uint32_t& d0, uint32_t& d1,
                                                  uint32_t& d2, uint32_t& d3,
                                                  uint32_t addr) {
    asm volatile("ldmatrix.sync.aligned.m8n8.x4.trans.shared.b16 {%0,%1,%2,%3}, [%4];"
        : "=r"(d0), "=r"(d1), "=r"(d2), "=r"(d3) : "r"(addr));
}
__device__ __forceinline__ void mma_bf16(float* c, const uint32_t* a,
                                         const uint32_t* b) {
    asm volatile(
        "mma.sync.aligned.m16n8k16.row.col.f32.bf16.bf16.f32 "
        "{%0,%1,%2,%3}, {%4,%5,%6,%7}, {%8,%9}, {%0,%1,%2,%3};"
        : "+f"(c[0]), "+f"(c[1]), "+f"(c[2]), "+f"(c[3])
        : "r"(a[0]), "r"(a[1]), "r"(a[2]), "r"(a[3]), "r"(b[0]), "r"(b[1]));
}

__device__ __forceinline__ uint32_t packbf(__nv_bfloat16 x, __nv_bfloat16 y) {
    __nv_bfloat162 p; p.x = x; p.y = y;
    return *reinterpret_cast<uint32_t*>(&p);
}
__device__ __forceinline__ void split2(float x, float y,
                                       uint32_t& hi, uint32_t& lo) {
    __nv_bfloat16 hx = __float2bfloat16_rn(x);
    __nv_bfloat16 hy = __float2bfloat16_rn(y);
    hi = packbf(hx, hy);
    lo = packbf(__float2bfloat16_rn(x - __bfloat162float(hx)),
                __float2bfloat16_rn(y - __bfloat162float(hy)));
}
__device__ __forceinline__ void split4(float4 v, uint2& hi, uint2& lo) {
    split2(v.x, v.y, hi.x, lo.x);
    split2(v.z, v.w, hi.y, lo.y);
}

// ===========================================================================
// Split kernel: fp32 -> bf16 hi/lo
// ===========================================================================
__global__ __launch_bounds__(256)
void split_kernel(const float* __restrict__ src,
                  __nv_bfloat16* __restrict__ h,
                  __nv_bfloat16* __restrict__ l, int n4)
{
    int i = blockIdx.x * 256 + threadIdx.x;
    if (i < n4) {
        float4 v = ((const float4*)src)[i];
        uint2 hi, lo;
        split4(v, hi, lo);
        ((uint2*)h)[i] = hi;
        ((uint2*)l)[i] = lo;
    }
}

// ===========================================================================
// All-bf16 cp.async GEMM:  C[m,n] = sum_k A[m,k] * W[n,k]
// 128x128 tile, BK=32, 3-stage pipeline, 8 warps (32x64 each).
// D = Ah*Bh + Ah*Bl + Al*Bh
// headMode=1: split result -> (Ch,Cl) in [B,NH,S,HD]; else fp32 -> Cf.
// ===========================================================================
#define GLDS 40            // bf16 elems per smem row (80 bytes)
#define GBUF (128 * 80)    // 10240 bytes per operand buffer
#define GSTAGE (4 * GBUF)  // 40960
#define GEMM_SMEM (3 * GSTAGE)

__global__ __launch_bounds__(256, 1)
void gemm_bf16_kernel(const __nv_bfloat16* __restrict__ Ah,
                      const __nv_bfloat16* __restrict__ Al,
                      const __nv_bfloat16* __restrict__ Bh,
                      const __nv_bfloat16* __restrict__ Bl,
                      __nv_bfloat16* __restrict__ Ch,
                      __nv_bfloat16* __restrict__ Cl,
                      float* __restrict__ Cf, int headMode)
{
    extern __shared__ char smc[];
    const uint32_t sb = smem_to_u32(smc);

    const int t    = threadIdx.x;
    const int lane = t & 31;
    const int wid  = t >> 5;
    const int wm   = wid & 3;
    const int wn   = wid >> 2;
    const int m0   = blockIdx.y << 7;
    const int n0   = blockIdx.x << 7;

    const int rA = lane & 15;
    const int cA = (lane >> 4) << 3;
    const int rB = (lane & 7) + ((lane >> 4) << 3);
    const int cB = lane & 8;

    // stage issue: 4 bufs x 128 rows x 8 chunks (8B each)
    auto issue = [&](int c, int stg) {
        const int k0 = c << 5;
        const uint32_t st = sb + stg * GSTAGE;
#pragma unroll
        for (int j = 0; j < 4; j++) {
            int idx = t + (j << 8);
            int row = idx >> 3, ch = idx & 7;
            uint32_t so = (uint32_t)(row * 80 + ch * 8);
            const __nv_bfloat16* g;
            g = Ah + (size_t)(m0 + row) * NHID + k0 + ch * 4;
            cp_async8(st + 0 * GBUF + so, g);
            g = Al + (size_t)(m0 + row) * NHID + k0 + ch * 4;
            cp_async8(st + 1 * GBUF + so, g);
            g = Bh + (size_t)(n0 + row) * NHID + k0 + ch * 4;
            cp_async8(st + 2 * GBUF + so, g);
            g = Bl + (size_t)(n0 + row) * NHID + k0 + ch * 4;
            cp_async8(st + 3 * GBUF + so, g);
        }
        cp_commit();
    };

    float acc[2][8][4];
#pragma unroll
    for (int mf = 0; mf < 2; mf++)
#pragma unroll
        for (int nf = 0; nf < 8; nf++)
#pragma unroll
            for (int r = 0; r < 4; r++) acc[mf][nf][r] = 0.f;

    issue(0, 0);
    issue(1, 1);

    for (int c = 0; c < 32; ++c) {
        if (c < 31) cp_wait<1>(); else cp_wait<0>();
        __syncthreads();
        if (c + 2 < 32) issue(c + 2, (c + 2) % 3);

        const uint32_t st = sb + (c % 3) * GSTAGE;
#pragma unroll
        for (int ks = 0; ks < 2; ks++) {
            const int k0 = ks << 4;
            uint32_t ah[2][4], al[2][4], bh[8][2], bl[8][2];
#pragma unroll
            for (int mf = 0; mf < 2; mf++) {
                uint32_t ro = (uint32_t)((wm * 32 + mf * 16 + rA) * GLDS + k0 + cA) * 2;
                ldmatrix_x4(ah[mf][0], ah[mf][1], ah[mf][2], ah[mf][3], st + 0 * GBUF + ro);
                ldmatrix_x4(al[mf][0], al[mf][1], al[mf][2], al[mf][3], st + 1 * GBUF + ro);
            }
#pragma unroll
            for (int p = 0; p < 4; p++) {
                uint32_t ro = (uint32_t)((wn * 64 + p * 16 + rB) * GLDS + k0 + cB) * 2;
                uint32_t d0, d1, d2, d3;
                ldmatrix_x4(d0, d1, d2, d3, st + 2 * GBUF + ro);
                bh[2 * p][0] = d0; bh[2 * p][1] = d1;
                bh[2 * p + 1][0] = d2; bh[2 * p + 1][1] = d3;
                ldmatrix_x4(d0, d1, d2, d3, st + 3 * GBUF + ro);
                bl[2 * p][0] = d0; bl[2 * p][1] = d1;
                bl[2 * p + 1][0] = d2; bl[2 * p + 1][1] = d3;
            }
#pragma unroll
            for (int mf = 0; mf < 2; mf++)
#pragma unroll
                for (int nf = 0; nf < 8; nf++) {
                    mma_bf16(acc[mf][nf], ah[mf], bh[nf]);
                    mma_bf16(acc[mf][nf], ah[mf], bl[nf]);
                    mma_bf16(acc[mf][nf], al[mf], bh[nf]);
                }
        }
    }

    // epilogue
    const int rowBase = m0 + wm * 32 + (lane >> 2);
    const int colBase = n0 + wn * 64 + ((lane & 3) << 1);
#pragma unroll
    for (int mf = 0; mf < 2; mf++) {
#pragma unroll
        for (int nf = 0; nf < 8; nf++) {
            int mA = rowBase + mf * 16;
            int n  = colBase + nf * 8;
            if (headMode) {
                int h = n >> 6, d = n & 63;
#pragma unroll
                for (int half = 0; half < 2; half++) {
                    int m = mA + half * 8;
                    int b = m >> 11, s = m & (NS - 1);
                    size_t idx = ((((size_t)(b * NHEADS + h)) * NS + s) << 6) + d;
                    uint32_t hi, lo;
                    split2(acc[mf][nf][half * 2], acc[mf][nf][half * 2 + 1], hi, lo);
                    *(uint32_t*)(Ch + idx) = hi;
                    *(uint32_t*)(Cl + idx) = lo;
                }
            } else {
#pragma unroll
                for (int half = 0; half < 2; half++) {
                    int m = mA + half * 8;
                    float2 v = make_float2(acc[mf][nf][half * 2],
                                           acc[mf][nf][half * 2 + 1]);
                    *(float2*)(Cf + (size_t)m * NHID + n) = v;
                }
            }
        }
    }
}

// ===========================================================================
// Tensor-core flash attention, cp.async double-buffered.
// CTA = (b,h) x 128 q-rows, 8 warps (16 rows each), K-tile 128.
// ===========================================================================
#define KT 128
#define ALDS 72                 // bf16 elems per row (144 bytes)
#define ABUF (128 * 144)        // 18432 per operand buffer
#define ASTG (4 * ABUF)         // stage: KH, KL, VH, VL
#define OQH 0
#define OQL ABUF
#define OST (2 * ABUF)          // 36864
#define OMSK (OST + 2 * ASTG)   // 184320
#define ATTN_SMEM (OMSK + 1024)

__global__ __launch_bounds__(256, 1)
void attn_tc_kernel(const float* __restrict__ mask)
{
    extern __shared__ char smc[];
    const uint32_t sb = smem_to_u32(smc);

    const int t    = threadIdx.x;
    const int lane = t & 31;
    const int w    = t >> 5;

    const int bh = blockIdx.y;
    const int b  = bh >> 4;
    const int h  = bh & 15;
    const int q0 = blockIdx.x << 7;

    const int rA = lane & 15;
    const int cA = (lane >> 4) << 3;
    const int rB = (lane & 7) + ((lane >> 4) << 3);
    const int cB = lane & 8;
    const int c0 = (lane & 3) << 1;

    const size_t qbase  = ((size_t)bh * NS + q0) * DHEAD;
    const size_t kvbase = (size_t)bh * NS * DHEAD;

    auto issue_kv = [&](int kt, int stg) {
        const size_t base = kvbase + (size_t)kt * KT * DHEAD;
        const uint32_t st = sb + OST + stg * ASTG;
#pragma unroll
        for (int j = 0; j < 4; j++) {
            int idx = t + (j << 8);
            int row = idx >> 3, ch = idx & 7;
            uint32_t so = (uint32_t)(row * 144 + ch * 16);
            size_t go = base + row * DHEAD + ch * 8;
            cp_async16(st + 0 * ABUF + so, g_kh + go);
            cp_async16(st + 1 * ABUF + so, g_kl + go);
            cp_async16(st + 2 * ABUF + so, g_vh + go);
            cp_async16(st + 3 * ABUF + so, g_vl + go);
        }
        if (t < 32)
            cp_async16(sb + OMSK + stg * 512 + t * 16,
                       mask + (size_t)b * NS + kt * KT + t * 4);
        cp_commit();
    };

    // prologue: Q (both halves) + KV stage 0 in one group
#pragma unroll
    for (int j = 0; j < 4; j++) {
        int idx = t + (j << 8);
        int row = idx >> 3, ch = idx & 7;
        uint32_t so = (uint32_t)(row * 144 + ch * 16);
        size_t go = qbase + row * DHEAD + ch * 8;
        cp_async16(sb + OQH + so, g_qh + go);
        cp_async16(sb + OQL + so, g_ql + go);
    }
    issue_kv(0, 0);

    float accs[16][4];
    float acco[8][4];
    float m0 = -INFINITY, m1 = -INFINITY, l0 = 0.f, l1 = 0.f;
#pragma unroll
    for (int nf = 0; nf < 8; nf++)
#pragma unroll
        for (int r = 0; r < 4; r++) acco[nf][r] = 0.f;

    for (int kt = 0; kt < NS / KT; kt++) {
        cp_wait<0>();
        __syncthreads();
        if (kt + 1 < NS / KT) issue_kv(kt + 1, (kt + 1) & 1);

        const int stg = kt & 1;
        const uint32_t st = sb + OST + stg * ASTG;
        const float* msk = (const float*)(smc + OMSK + stg * 512);

        // ---- S = Q K^T ----
#pragma unroll
        for (int nf = 0; nf < 16; nf++)
#pragma unroll
            for (int r = 0; r < 4; r++) accs[nf][r] = 0.f;

#pragma unroll
        for (int ks = 0; ks < 4; ks++) {
            uint32_t aqh[4], aql[4];
            uint32_t qo = (uint32_t)((w * 16 + rA) * ALDS + ks * 16 + cA) * 2;
            ldmatrix_x4(aqh[0], aqh[1], aqh[2], aqh[3], sb + OQH + qo);
            ldmatrix_x4(aql[0], aql[1], aql[2], aql[3], sb + OQL + qo);
#pragma unroll
            for (int p = 0; p < 8; p++) {
                uint32_t ko = (uint32_t)((p * 16 + rB) * ALDS + ks * 16 + cB) * 2;
                uint32_t h0, h1, h2, h3, e0, e1, e2, e3;
                ldmatrix_x4(h0, h1, h2, h3, st + 0 * ABUF + ko);
                ldmatrix_x4(e0, e1, e2, e3, st + 1 * ABUF + ko);
                uint32_t bhi0[2] = {h0, h1}, bhi1[2] = {h2, h3};
                uint32_t blo0[2] = {e0, e1}, blo1[2] = {e2, e3};
                mma_bf16(accs[2 * p],     aqh, bhi0);
                mma_bf16(accs[2 * p],     aqh, blo0);
                mma_bf16(accs[2 * p],     aql, bhi0);
                mma_bf16(accs[2 * p + 1], aqh, bhi1);
                mma_bf16(accs[2 * p + 1], aqh, blo1);
                mma_bf16(accs[2 * p + 1], aql, bhi1);
            }
        }

        // ---- scale + mask ----
#pragma unroll
        for (int nf = 0; nf < 16; nf++) {
            float mk0 = msk[nf * 8 + c0];
            float mk1 = msk[nf * 8 + c0 + 1];
            accs[nf][0] = fmaf(accs[nf][0], 0.125f, mk0);
            accs[nf][1] = fmaf(accs[nf][1], 0.125f, mk1);
            accs[nf][2] = fmaf(accs[nf][2], 0.125f, mk0);
            accs[nf][3] = fmaf(accs[nf][3], 0.125f, mk1);
        }

        // ---- online softmax ----
        float tm0 = -INFINITY, tm1 = -INFINITY;
#pragma unroll
        for (int nf = 0; nf < 16; nf++) {
            tm0 = fmaxf(tm0, fmaxf(accs[nf][0], accs[nf][1]));
            tm1 = fmaxf(tm1, fmaxf(accs[nf][2], accs[nf][3]));
        }
        tm0 = fmaxf(tm0, __shfl_xor_sync(0xffffffffu, tm0, 1));
        tm0 = fmaxf(tm0, __shfl_xor_sync(0xffffffffu, tm0, 2));
        tm1 = fmaxf(tm1, __shfl_xor_sync(0xffffffffu, tm1, 1));
        tm1 = fmaxf(tm1, __shfl_xor_sync(0xffffffffu, tm1, 2));

        float mn0 = fmaxf(m0, tm0), mn1 = fmaxf(m1, tm1);
        float cr0 = __expf(m0 - mn0), cr1 = __expf(m1 - mn1);
        m0 = mn0; m1 = mn1;

        float rs0 = 0.f, rs1 = 0.f;
#pragma unroll
        for (int nf = 0; nf < 16; nf++) {
            accs[nf][0] = __expf(accs[nf][0] - mn0);
            accs[nf][1] = __expf(accs[nf][1] - mn0);
            accs[nf][2] = __expf(accs[nf][2] - mn1);
            accs[nf][3] = __expf(accs[nf][3] - mn1);
            rs0 += accs[nf][0] + accs[nf][1];
            rs1 += accs[nf][2] + accs[nf][3];
        }
        rs0 += __shfl_xor_sync(0xffffffffu, rs0, 1);
        rs0 += __shfl_xor_sync(0xffffffffu, rs0, 2);
        rs1 += __shfl_xor_sync(0xffffffffu, rs1, 1);
        rs1 += __shfl_xor_sync(0xffffffffu, rs1, 2);
        l0 = l0 * cr0 + rs0;
        l1 = l1 * cr1 + rs1;

#pragma unroll
        for (int nf = 0; nf < 8; nf++) {
            acco[nf][0] *= cr0; acco[nf][1] *= cr0;
            acco[nf][2] *= cr1; acco[nf][3] *= cr1;
        }

        // ---- O += P V ----
#pragma unroll
        for (int kc = 0; kc < 8; kc++) {
            uint32_t aph[4], apl[4];
            split2(accs[2 * kc][0],     accs[2 * kc][1],     aph[0], apl[0]);
            split2(accs[2 * kc][2],     accs[2 * kc][3],     aph[1], apl[1]);
            split2(accs[2 * kc + 1][0], accs[2 * kc + 1][1], aph[2], apl[2]);
            split2(accs[2 * kc + 1][2], accs[2 * kc + 1][3], aph[3], apl[3]);
#pragma unroll
            for (int pv = 0; pv < 4; pv++) {
                uint32_t vo = (uint32_t)((kc * 16 + rA) * ALDS + pv * 16 + cA) * 2;
                uint32_t h0, h1, h2, h3, e0, e1, e2, e3;
                ldmatrix_x4_trans(h0, h1, h2, h3, st + 2 * ABUF + vo);
                ldmatrix_x4_trans(e0, e1, e2, e3, st + 3 * ABUF + vo);
                uint32_t bvh0[2] = {h0, h1}, bvh1[2] = {h2, h3};
                uint32_t bvl0[2] = {e0, e1}, bvl1[2] = {e2, e3};
                mma_bf16(acco[2 * pv],     aph, bvh0);
                mma_bf16(acco[2 * pv],     aph, bvl0);
                mma_bf16(acco[2 * pv],     apl, bvh0);
                mma_bf16(acco[2 * pv + 1], aph, bvh1);
                mma_bf16(acco[2 * pv + 1], aph, bvl1);
                mma_bf16(acco[2 * pv + 1], apl, bvh1);
            }
        }
    }

    // ---- epilogue: normalize, split, write bf16 hi/lo [B,S,H] ----
    float inv0 = 1.f / l0;
    float inv1 = 1.f / l1;
    int row0 = q0 + w * 16 + (lane >> 2);
#pragma unroll
    for (int nf = 0; nf < 8; nf++) {
        int d = nf * 8 + c0;
        size_t i0 = ((size_t)(b * NS) + row0) * NHID + h * DHEAD + d;
        size_t i1 = i0 + (size_t)8 * NHID;
        uint32_t hi, lo;
        split2(acco[nf][0] * inv0, acco[nf][1] * inv0, hi, lo);
        *(uint32_t*)(g_ah + i0) = hi;
        *(uint32_t*)(g_al + i0) = lo;
        split2(acco[nf][2] * inv1, acco[nf][3] * inv1, hi, lo);
        *(uint32_t*)(g_ah + i1) = hi;
        *(uint32_t*)(g_al + i1) = lo;
    }
}

// ---------------------------------------------------------------------------
// Launch
// ---------------------------------------------------------------------------
extern "C" void kernel_launch(void* const* d_in, const int* in_sizes, int n_in,
                              void* d_out, int out_size)
{
    const float* X    = (const float*)d_in[0];
    const float* mask = (const float*)d_in[1];
    const float* Wq   = (const float*)d_in[2];
    const float* Wk   = (const float*)d_in[3];
    const float* Wv   = (const float*)d_in[4];
    const float* Wo   = (const float*)d_in[5];
    float* out = (float*)d_out;

    __nv_bfloat16 *xh, *xl, *wqh, *wql, *wkh, *wkl, *wvh, *wvl, *woh, *wol;
    __nv_bfloat16 *qh, *ql, *kh, *kl, *vh, *vl, *ah, *al;
    cudaGetSymbolAddress((void**)&xh, g_xh);   cudaGetSymbolAddress((void**)&xl, g_xl);
    cudaGetSymbolAddress((void**)&wqh, g_wqh); cudaGetSymbolAddress((void**)&wql, g_wql);
    cudaGetSymbolAddress((void**)&wkh, g_wkh); cudaGetSymbolAddress((void**)&wkl, g_wkl);
    cudaGetSymbolAddress((void**)&wvh, g_wvh); cudaGetSymbolAddress((void**)&wvl, g_wvl);
    cudaGetSymbolAddress((void**)&woh, g_woh); cudaGetSymbolAddress((void**)&wol, g_wol);
    cudaGetSymbolAddress((void**)&qh, g_qh);   cudaGetSymbolAddress((void**)&ql, g_ql);
    cudaGetSymbolAddress((void**)&kh, g_kh);   cudaGetSymbolAddress((void**)&kl, g_kl);
    cudaGetSymbolAddress((void**)&vh, g_vh);   cudaGetSymbolAddress((void**)&vl, g_vl);
    cudaGetSymbolAddress((void**)&ah, g_ah);   cudaGetSymbolAddress((void**)&al, g_al);

    cudaFuncSetAttribute(gemm_bf16_kernel,
                         cudaFuncAttributeMaxDynamicSharedMemorySize, GEMM_SMEM);
    cudaFuncSetAttribute(attn_tc_kernel,
                         cudaFuncAttributeMaxDynamicSharedMemorySize, ATTN_SMEM);

    // pre-split inputs
    int n4x = MTOT * NHID / 4;
    int n4w = NHID * NHID / 4;
    split_kernel<<<n4x / 256, 256>>>(X,  xh,  xl,  n4x);
    split_kernel<<<n4w / 256, 256>>>(Wq, wqh, wql, n4w);
    split_kernel<<<n4w / 256, 256>>>(Wk, wkh, wkl, n4w);
    split_kernel<<<n4w / 256, 256>>>(Wv, wvh, wvl, n4w);
    split_kernel<<<n4w / 256, 256>>>(Wo, woh, wol, n4w);

    dim3 gg(NHID / 128, MTOT / 128);   // 8 x 64
    gemm_bf16_kernel<<<gg, 256, GEMM_SMEM>>>(xh, xl, wqh, wql, qh, ql, nullptr, 1);
    gemm_bf16_kernel<<<gg, 256, GEMM_SMEM>>>(xh, xl, wkh, wkl, kh, kl, nullptr, 1);
    gemm_bf16_kernel<<<gg, 256, GEMM_SMEM>>>(xh, xl, wvh, wvl, vh, vl, nullptr, 1);

    dim3 ga(NS / 128, NB * NHEADS);    // 16 x 64
    attn_tc_kernel<<<ga, 256, ATTN_SMEM>>>(mask);

    gemm_bf16_kernel<<<gg, 256, GEMM_SMEM>>>(ah, al, woh, wol, nullptr, nullptr, out, 0);
}

// round 6
// speedup vs baseline: 3.2433x; 1.0597x over previous
#include <cuda_runtime.h>
#include <cuda_bf16.h>
#include <cstdint>
#include <math.h>

#define NB 4
#define NS 2048
#define NHID 1024
#define NHEADS 16
#define DHEAD 64
#define MTOT (NB * NS)   // 8192

// ---------------------------------------------------------------------------
// Global scratch (bf16 hi/lo pairs everywhere)
// ---------------------------------------------------------------------------
__device__ __nv_bfloat16 g_xh[MTOT * NHID], g_xl[MTOT * NHID];
__device__ __nv_bfloat16 g_wh[3 * NHID * NHID], g_wl[3 * NHID * NHID];   // Wq|Wk|Wv
__device__ __nv_bfloat16 g_woh[NHID * NHID], g_wol[NHID * NHID];
__device__ __nv_bfloat16 g_qh[NB * NHEADS * NS * DHEAD], g_ql[NB * NHEADS * NS * DHEAD];
__device__ __nv_bfloat16 g_kh[NB * NHEADS * NS * DHEAD], g_kl[NB * NHEADS * NS * DHEAD];
__device__ __nv_bfloat16 g_vh[NB * NHEADS * NS * DHEAD], g_vl[NB * NHEADS * NS * DHEAD];
__device__ __nv_bfloat16 g_ah[MTOT * NHID], g_al[MTOT * NHID];

// ===========================================================================
// Helpers
// ===========================================================================
__device__ __forceinline__ uint32_t smem_to_u32(const void* p) {
    uint32_t a;
    asm("{ .reg .u64 t; cvta.to.shared.u64 t, %1; cvt.u32.u64 %0, t; }"
        : "=r"(a) : "l"(p));
    return a;
}
__device__ __forceinline__ void cp_async16(uint32_t s, const void* g) {
    asm volatile("cp.async.cg.shared.global [%0], [%1], 16;" :: "r"(s), "l"(g));
}
__device__ __forceinline__ void cp_commit() {
    asm volatile("cp.async.commit_group;" ::: "memory");
}
template <int N>
__device__ __forceinline__ void cp_wait() {
    asm volatile("cp.async.wait_group %0;" :: "n"(N) : "memory");
}
__device__ __forceinline__ void ldmatrix_x4(uint32_t& d0, uint32_t& d1,
                                            uint32_t& d2, uint32_t& d3,
                                            uint32_t addr) {
    asm volatile("ldmatrix.sync.aligned.m8n8.x4.shared.b16 {%0,%1,%2,%3}, [%4];"
        : "=r"(d0), "=r"(d1), "=r"(d2), "=r"(d3) : "r"(addr));
}
__device__ __forceinline__ void ldmatrix_x4_trans(uint32_t& d0, uint32_t& d1,
                                                  uint32_t& d2, uint32_t& d3,
                                                  uint32_t addr) {
    asm volatile("ldmatrix.sync.aligned.m8n8.x4.trans.shared.b16 {%0,%1,%2,%3}, [%4];"
        : "=r"(d0), "=r"(d1), "=r"(d2), "=r"(d3) : "r"(addr));
}
__device__ __forceinline__ void mma_bf16(float* c, const uint32_t* a,
                                         const uint32_t* b) {
    asm volatile(
        "mma.sync.aligned.m16n8k16.row.col.f32.bf16.bf16.f32 "
        "{%0,%1,%2,%3}, {%4,%5,%6,%7}, {%8,%9}, {%0,%1,%2,%3};"
        : "+f"(c[0]), "+f"(c[1]), "+f"(c[2]), "+f"(c[3])
        : "r"(a[0]), "r"(a[1]), "r"(a[2]), "r"(a[3]), "r"(b[0]), "r"(b[1]));
}
__device__ __forceinline__ uint32_t packbf(__nv_bfloat16 x, __nv_bfloat16 y) {
    __nv_bfloat162 p; p.x = x; p.y = y;
    return *reinterpret_cast<uint32_t*>(&p);
}
__device__ __forceinline__ void split2(float x, float y,
                                       uint32_t& hi, uint32_t& lo) {
    __nv_bfloat16 hx = __float2bfloat16_rn(x);
    __nv_bfloat16 hy = __float2bfloat16_rn(y);
    hi = packbf(hx, hy);
    lo = packbf(__float2bfloat16_rn(x - __bfloat162float(hx)),
                __float2bfloat16_rn(y - __bfloat162float(hy)));
}
__device__ __forceinline__ void split4(float4 v, uint2& hi, uint2& lo) {
    split2(v.x, v.y, hi.x, lo.x);
    split2(v.z, v.w, hi.y, lo.y);
}

// ===========================================================================
// Split kernel: fp32 -> bf16 hi/lo
// ===========================================================================
__global__ __launch_bounds__(256)
void split_kernel(const float* __restrict__ src,
                  __nv_bfloat16* __restrict__ h,
                  __nv_bfloat16* __restrict__ l, int n4)
{
    int i = blockIdx.x * 256 + threadIdx.x;
    if (i < n4) {
        float4 v = ((const float4*)src)[i];
        uint2 hi, lo;
        split4(v, hi, lo);
        ((uint2*)h)[i] = hi;
        ((uint2*)l)[i] = lo;
    }
}

// ===========================================================================
// All-bf16 cp.async GEMM: CTA tile 128x256, warp tile 64x64, BK=32, 3 stages.
// C[m,n] = sum_k A[m,k]*B[n,k];  D = Ah*Bh + Ah*Bl + Al*Bh
// qkvMode=1: B is [3072,1024] (Wq|Wk|Wv); scatter split output into
//            g_{q,k,v}{h,l} in [B,NH,S,HD]; Q scaled by 0.125.
// qkvMode=0: fp32 output to Cf [M,1024].
// ===========================================================================
#define GLDS 40
#define GA_BUF 10240           // 128 rows x 80B
#define GB_BUF 20480           // 256 rows x 80B
#define GSTAGE (2 * GA_BUF + 2 * GB_BUF)   // 61440
#define GEMM_SMEM (3 * GSTAGE)             // 184320

__global__ __launch_bounds__(256, 1)
void gemm_bf16_kernel(const __nv_bfloat16* __restrict__ Ah,
                      const __nv_bfloat16* __restrict__ Al,
                      const __nv_bfloat16* __restrict__ Bh,
                      const __nv_bfloat16* __restrict__ Bl,
                      float* __restrict__ Cf, int qkvMode)
{
    extern __shared__ char smc[];
    const uint32_t sb = smem_to_u32(smc);

    const int t    = threadIdx.x;
    const int lane = t & 31;
    const int wid  = t >> 5;
    const int wm   = wid & 1;          // 2 M-warps (64 rows)
    const int wn   = wid >> 1;         // 4 N-warps (64 cols)
    const int m0   = blockIdx.y << 7;
    const int n0   = blockIdx.x << 8;

    const int rA = lane & 15;
    const int cA = (lane >> 4) << 3;
    const int rB = (lane & 7) + ((lane >> 4) << 3);
    const int cB = lane & 8;

    auto issue = [&](int c, int stg) {
        const int k0 = c << 5;
        const uint32_t st = sb + stg * GSTAGE;
#pragma unroll
        for (int j = 0; j < 2; j++) {              // A: 128 rows x 4 chunks
            int idx = t + (j << 8);
            int row = idx >> 2, ch = idx & 3;
            uint32_t so = (uint32_t)(row * 80 + ch * 16);
            const size_t go = (size_t)(m0 + row) * NHID + k0 + ch * 8;
            cp_async16(st + so, Ah + go);
            cp_async16(st + GA_BUF + so, Al + go);
        }
#pragma unroll
        for (int j = 0; j < 4; j++) {              // B: 256 rows x 4 chunks
            int idx = t + (j << 8);
            int row = idx >> 2, ch = idx & 3;
            uint32_t so = (uint32_t)(row * 80 + ch * 16);
            const size_t go = (size_t)(n0 + row) * NHID + k0 + ch * 8;
            cp_async16(st + 2 * GA_BUF + so, Bh + go);
            cp_async16(st + 2 * GA_BUF + GB_BUF + so, Bl + go);
        }
        cp_commit();
    };

    float acc[4][8][4];
#pragma unroll
    for (int mf = 0; mf < 4; mf++)
#pragma unroll
        for (int nf = 0; nf < 8; nf++)
#pragma unroll
            for (int r = 0; r < 4; r++) acc[mf][nf][r] = 0.f;

    issue(0, 0);
    issue(1, 1);

    for (int c = 0; c < 32; ++c) {
        if (c < 31) cp_wait<1>(); else cp_wait<0>();
        __syncthreads();
        if (c + 2 < 32) issue(c + 2, (c + 2) % 3);

        const uint32_t st = sb + (c % 3) * GSTAGE;
#pragma unroll
        for (int ks = 0; ks < 2; ks++) {
            const int k0 = ks << 4;
            uint32_t ah[4][4], al[4][4];
#pragma unroll
            for (int mf = 0; mf < 4; mf++) {
                uint32_t ro = (uint32_t)((wm * 64 + mf * 16 + rA) * GLDS + k0 + cA) * 2;
                ldmatrix_x4(ah[mf][0], ah[mf][1], ah[mf][2], ah[mf][3], st + ro);
                ldmatrix_x4(al[mf][0], al[mf][1], al[mf][2], al[mf][3], st + GA_BUF + ro);
            }
#pragma unroll
            for (int p = 0; p < 4; p++) {
                uint32_t ro = (uint32_t)((wn * 64 + p * 16 + rB) * GLDS + k0 + cB) * 2;
                uint32_t h0, h1, h2, h3, e0, e1, e2, e3;
                ldmatrix_x4(h0, h1, h2, h3, st + 2 * GA_BUF + ro);
                ldmatrix_x4(e0, e1, e2, e3, st + 2 * GA_BUF + GB_BUF + ro);
                uint32_t bh0[2] = {h0, h1}, bh1[2] = {h2, h3};
                uint32_t bl0[2] = {e0, e1}, bl1[2] = {e2, e3};
#pragma unroll
                for (int mf = 0; mf < 4; mf++) {
                    mma_bf16(acc[mf][2 * p],     ah[mf], bh0);
                    mma_bf16(acc[mf][2 * p],     ah[mf], bl0);
                    mma_bf16(acc[mf][2 * p],     al[mf], bh0);
                    mma_bf16(acc[mf][2 * p + 1], ah[mf], bh1);
                    mma_bf16(acc[mf][2 * p + 1], ah[mf], bl1);
                    mma_bf16(acc[mf][2 * p + 1], al[mf], bh1);
                }
            }
        }
    }

    // ---- epilogue ----
    const int rowBase = m0 + wm * 64 + (lane >> 2);
    const int colBase = n0 + wn * 64 + ((lane & 3) << 1);

    if (qkvMode) {
        const int which = n0 >> 10;     // constant per CTA (256 | 1024)
        __nv_bfloat16 *dh, *dl;
        if (which == 0)      { dh = g_qh; dl = g_ql; }
        else if (which == 1) { dh = g_kh; dl = g_kl; }
        else                 { dh = g_vh; dl = g_vl; }
        const float sc = (which == 0) ? 0.125f : 1.0f;
#pragma unroll
        for (int mf = 0; mf < 4; mf++)
#pragma unroll
            for (int nf = 0; nf < 8; nf++) {
                int n = colBase + nf * 8;
                int r = n & 1023;
                int h = r >> 6, d = r & 63;
#pragma unroll
                for (int half = 0; half < 2; half++) {
                    int m = rowBase + mf * 16 + half * 8;
                    int b = m >> 11, s = m & (NS - 1);
                    size_t idx = ((((size_t)(b * NHEADS + h)) * NS + s) << 6) + d;
                    uint32_t hi, lo;
                    split2(acc[mf][nf][half * 2] * sc,
                           acc[mf][nf][half * 2 + 1] * sc, hi, lo);
                    *(uint32_t*)(dh + idx) = hi;
                    *(uint32_t*)(dl + idx) = lo;
                }
            }
    } else {
#pragma unroll
        for (int mf = 0; mf < 4; mf++)
#pragma unroll
            for (int nf = 0; nf < 8; nf++) {
                int n = colBase + nf * 8;
#pragma unroll
                for (int half = 0; half < 2; half++) {
                    int m = rowBase + mf * 16 + half * 8;
                    *(float2*)(Cf + (size_t)m * NHID + n) =
                        make_float2(acc[mf][nf][half * 2], acc[mf][nf][half * 2 + 1]);
                }
            }
    }
}

// ===========================================================================
// Tensor-core flash attention, cp.async double-buffered.
// CTA = (b,h) x 128 q-rows, 8 warps (16 rows each), K-tile 128.
// Q pre-scaled by 0.125 at QKV epilogue.
// ===========================================================================
#define KT 128
#define ALDS 72
#define ABUF (128 * 144)
#define ASTG (4 * ABUF)
#define OQH 0
#define OQL ABUF
#define OST (2 * ABUF)
#define OMSK (OST + 2 * ASTG)
#define ATTN_SMEM (OMSK + 1024)

__global__ __launch_bounds__(256, 1)
void attn_tc_kernel(const float* __restrict__ mask)
{
    extern __shared__ char smc[];
    const uint32_t sb = smem_to_u32(smc);

    const int t    = threadIdx.x;
    const int lane = t & 31;
    const int w    = t >> 5;

    const int bh = blockIdx.y;
    const int b  = bh >> 4;
    const int h  = bh & 15;
    const int q0 = blockIdx.x << 7;

    const int rA = lane & 15;
    const int cA = (lane >> 4) << 3;
    const int rB = (lane & 7) + ((lane >> 4) << 3);
    const int cB = lane & 8;
    const int c0 = (lane & 3) << 1;

    const size_t qbase  = ((size_t)bh * NS + q0) * DHEAD;
    const size_t kvbase = (size_t)bh * NS * DHEAD;

    auto issue_kv = [&](int kt, int stg) {
        const size_t base = kvbase + (size_t)kt * KT * DHEAD;
        const uint32_t st = sb + OST + stg * ASTG;
#pragma unroll
        for (int j = 0; j < 4; j++) {
            int idx = t + (j << 8);
            int row = idx >> 3, ch = idx & 7;
            uint32_t so = (uint32_t)(row * 144 + ch * 16);
            size_t go = base + row * DHEAD + ch * 8;
            cp_async16(st + 0 * ABUF + so, g_kh + go);
            cp_async16(st + 1 * ABUF + so, g_kl + go);
            cp_async16(st + 2 * ABUF + so, g_vh + go);
            cp_async16(st + 3 * ABUF + so, g_vl + go);
        }
        if (t < 32)
            cp_async16(sb + OMSK + stg * 512 + t * 16,
                       mask + (size_t)b * NS + kt * KT + t * 4);
        cp_commit();
    };

#pragma unroll
    for (int j = 0; j < 4; j++) {
        int idx = t + (j << 8);
        int row = idx >> 3, ch = idx & 7;
        uint32_t so = (uint32_t)(row * 144 + ch * 16);
        size_t go = qbase + row * DHEAD + ch * 8;
        cp_async16(sb + OQH + so, g_qh + go);
        cp_async16(sb + OQL + so, g_ql + go);
    }
    issue_kv(0, 0);

    float accs[16][4];
    float acco[8][4];
    float m0 = -INFINITY, m1 = -INFINITY, l0 = 0.f, l1 = 0.f;
#pragma unroll
    for (int nf = 0; nf < 8; nf++)
#pragma unroll
        for (int r = 0; r < 4; r++) acco[nf][r] = 0.f;

    for (int kt = 0; kt < NS / KT; kt++) {
        cp_wait<0>();
        __syncthreads();
        if (kt + 1 < NS / KT) issue_kv(kt + 1, (kt + 1) & 1);

        const int stg = kt & 1;
        const uint32_t st = sb + OST + stg * ASTG;
        const float* msk = (const float*)(smc + OMSK + stg * 512);

        // ---- S = Q K^T (Q pre-scaled) ----
#pragma unroll
        for (int nf = 0; nf < 16; nf++)
#pragma unroll
            for (int r = 0; r < 4; r++) accs[nf][r] = 0.f;

#pragma unroll
        for (int ks = 0; ks < 4; ks++) {
            uint32_t aqh[4], aql[4];
            uint32_t qo = (uint32_t)((w * 16 + rA) * ALDS + ks * 16 + cA) * 2;
            ldmatrix_x4(aqh[0], aqh[1], aqh[2], aqh[3], sb + OQH + qo);
            ldmatrix_x4(aql[0], aql[1], aql[2], aql[3], sb + OQL + qo);
#pragma unroll
            for (int p = 0; p < 8; p++) {
                uint32_t ko = (uint32_t)((p * 16 + rB) * ALDS + ks * 16 + cB) * 2;
                uint32_t h0, h1, h2, h3, e0, e1, e2, e3;
                ldmatrix_x4(h0, h1, h2, h3, st + 0 * ABUF + ko);
                ldmatrix_x4(e0, e1, e2, e3, st + 1 * ABUF + ko);
                uint32_t bhi0[2] = {h0, h1}, bhi1[2] = {h2, h3};
                uint32_t blo0[2] = {e0, e1}, blo1[2] = {e2, e3};
                mma_bf16(accs[2 * p],     aqh, bhi0);
                mma_bf16(accs[2 * p],     aqh, blo0);
                mma_bf16(accs[2 * p],     aql, bhi0);
                mma_bf16(accs[2 * p + 1], aqh, bhi1);
                mma_bf16(accs[2 * p + 1], aqh, blo1);
                mma_bf16(accs[2 * p + 1], aql, bhi1);
            }
        }

        // ---- + mask ----
#pragma unroll
        for (int nf = 0; nf < 16; nf++) {
            float mk0 = msk[nf * 8 + c0];
            float mk1 = msk[nf * 8 + c0 + 1];
            accs[nf][0] += mk0;
            accs[nf][1] += mk1;
            accs[nf][2] += mk0;
            accs[nf][3] += mk1;
        }

        // ---- online softmax ----
        float tm0 = -INFINITY, tm1 = -INFINITY;
#pragma unroll
        for (int nf = 0; nf < 16; nf++) {
            tm0 = fmaxf(tm0, fmaxf(accs[nf][0], accs[nf][1]));
            tm1 = fmaxf(tm1, fmaxf(accs[nf][2], accs[nf][3]));
        }
        tm0 = fmaxf(tm0, __shfl_xor_sync(0xffffffffu, tm0, 1));
        tm0 = fmaxf(tm0, __shfl_xor_sync(0xffffffffu, tm0, 2));
        tm1 = fmaxf(tm1, __shfl_xor_sync(0xffffffffu, tm1, 1));
        tm1 = fmaxf(tm1, __shfl_xor_sync(0xffffffffu, tm1, 2));

        float mn0 = fmaxf(m0, tm0), mn1 = fmaxf(m1, tm1);
        float cr0 = __expf(m0 - mn0), cr1 = __expf(m1 - mn1);
        m0 = mn0; m1 = mn1;

        float rs0 = 0.f, rs1 = 0.f;
#pragma unroll
        for (int nf = 0; nf < 16; nf++) {
            accs[nf][0] = __expf(accs[nf][0] - mn0);
            accs[nf][1] = __expf(accs[nf][1] - mn0);
            accs[nf][2] = __expf(accs[nf][2] - mn1);
            accs[nf][3] = __expf(accs[nf][3] - mn1);
            rs0 += accs[nf][0] + accs[nf][1];
            rs1 += accs[nf][2] + accs[nf][3];
        }
        rs0 += __shfl_xor_sync(0xffffffffu, rs0, 1);
        rs0 += __shfl_xor_sync(0xffffffffu, rs0, 2);
        rs1 += __shfl_xor_sync(0xffffffffu, rs1, 1);
        rs1 += __shfl_xor_sync(0xffffffffu, rs1, 2);
        l0 = l0 * cr0 + rs0;
        l1 = l1 * cr1 + rs1;

#pragma unroll
        for (int nf = 0; nf < 8; nf++) {
            acco[nf][0] *= cr0; acco[nf][1] *= cr0;
            acco[nf][2] *= cr1; acco[nf][3] *= cr1;
        }

        // ---- O += P V ----
#pragma unroll
        for (int kc = 0; kc < 8; kc++) {
            uint32_t aph[4], apl[4];
            split2(accs[2 * kc][0],     accs[2 * kc][1],     aph[0], apl[0]);
            split2(accs[2 * kc][2],     accs[2 * kc][3],     aph[1], apl[1]);
            split2(accs[2 * kc + 1][0], accs[2 * kc + 1][1], aph[2], apl[2]);
            split2(accs[2 * kc + 1][2], accs[2 * kc + 1][3], aph[3], apl[3]);
#pragma unroll
            for (int pv = 0; pv < 4; pv++) {
                uint32_t vo = (uint32_t)((kc * 16 + rA) * ALDS + pv * 16 + cA) * 2;
                uint32_t h0, h1, h2, h3, e0, e1, e2, e3;
                ldmatrix_x4_trans(h0, h1, h2, h3, st + 2 * ABUF + vo);
                ldmatrix_x4_trans(e0, e1, e2, e3, st + 3 * ABUF + vo);
                uint32_t bvh0[2] = {h0, h1}, bvh1[2] = {h2, h3};
                uint32_t bvl0[2] = {e0, e1}, bvl1[2] = {e2, e3};
                mma_bf16(acco[2 * pv],     aph, bvh0);
                mma_bf16(acco[2 * pv],     aph, bvl0);
                mma_bf16(acco[2 * pv],     apl, bvh0);
                mma_bf16(acco[2 * pv + 1], aph, bvh1);
                mma_bf16(acco[2 * pv + 1], aph, bvl1);
                mma_bf16(acco[2 * pv + 1], apl, bvh1);
            }
        }
    }

    // ---- epilogue ----
    float inv0 = 1.f / l0;
    float inv1 = 1.f / l1;
    int row0 = q0 + w * 16 + (lane >> 2);
#pragma unroll
    for (int nf = 0; nf < 8; nf++) {
        int d = nf * 8 + c0;
        size_t i0 = ((size_t)(b * NS) + row0) * NHID + h * DHEAD + d;
        size_t i1 = i0 + (size_t)8 * NHID;
        uint32_t hi, lo;
        split2(acco[nf][0] * inv0, acco[nf][1] * inv0, hi, lo);
        *(uint32_t*)(g_ah + i0) = hi;
        *(uint32_t*)(g_al + i0) = lo;
        split2(acco[nf][2] * inv1, acco[nf][3] * inv1, hi, lo);
        *(uint32_t*)(g_ah + i1) = hi;
        *(uint32_t*)(g_al + i1) = lo;
    }
}

// ---------------------------------------------------------------------------
// Launch
// ---------------------------------------------------------------------------
extern "C" void kernel_launch(void* const* d_in, const int* in_sizes, int n_in,
                              void* d_out, int out_size)
{
    const float* X    = (const float*)d_in[0];
    const float* mask = (const float*)d_in[1];
    const float* Wq   = (const float*)d_in[2];
    const float* Wk   = (const float*)d_in[3];
    const float* Wv   = (const float*)d_in[4];
    const float* Wo   = (const float*)d_in[5];
    float* out = (float*)d_out;

    __nv_bfloat16 *xh, *xl, *wh, *wl, *woh, *wol, *ah, *al;
    cudaGetSymbolAddress((void**)&xh, g_xh);   cudaGetSymbolAddress((void**)&xl, g_xl);
    cudaGetSymbolAddress((void**)&wh, g_wh);   cudaGetSymbolAddress((void**)&wl, g_wl);
    cudaGetSymbolAddress((void**)&woh, g_woh); cudaGetSymbolAddress((void**)&wol, g_wol);
    cudaGetSymbolAddress((void**)&ah, g_ah);   cudaGetSymbolAddress((void**)&al, g_al);

    cudaFuncSetAttribute(gemm_bf16_kernel,
                         cudaFuncAttributeMaxDynamicSharedMemorySize, GEMM_SMEM);
    cudaFuncSetAttribute(attn_tc_kernel,
                         cudaFuncAttributeMaxDynamicSharedMemorySize, ATTN_SMEM);

    int n4x = MTOT * NHID / 4;
    int n4w = NHID * NHID / 4;
    split_kernel<<<n4x / 256, 256>>>(X,  xh,  xl,  n4x);
    split_kernel<<<n4w / 256, 256>>>(Wq, wh,              wl,              n4w);
    split_kernel<<<n4w / 256, 256>>>(Wk, wh + NHID*NHID,  wl + NHID*NHID,  n4w);
    split_kernel<<<n4w / 256, 256>>>(Wv, wh + 2*NHID*NHID, wl + 2*NHID*NHID, n4w);
    split_kernel<<<n4w / 256, 256>>>(Wo, woh, wol, n4w);

    // fused QKV GEMM: [8192,1024] x [3072,1024]^T
    dim3 gq(3 * NHID / 256, MTOT / 128);   // 12 x 64
    gemm_bf16_kernel<<<gq, 256, GEMM_SMEM>>>(xh, xl, wh, wl, nullptr, 1);

    dim3 ga(NS / 128, NB * NHEADS);        // 16 x 64
    attn_tc_kernel<<<ga, 256, ATTN_SMEM>>>(mask);

    // output GEMM: [8192,1024] x [1024,1024]^T -> fp32 out
    dim3 go(NHID / 256, MTOT / 128);       // 4 x 64
    gemm_bf16_kernel<<<go, 256, GEMM_SMEM>>>(ah, al, woh, wol, out, 0);
}

// round 7
// speedup vs baseline: 3.4841x; 1.0742x over previous
#include <cuda_runtime.h>
#include <cuda_bf16.h>
#include <cuda_fp16.h>
#include <cstdint>
#include <math.h>

#define NB 4
#define NS 2048
#define NHID 1024
#define NHEADS 16
#define DHEAD 64
#define MTOT (NB * NS)   // 8192

// ---------------------------------------------------------------------------
// Global scratch
// ---------------------------------------------------------------------------
__device__ __nv_bfloat16 g_xh[MTOT * NHID], g_xl[MTOT * NHID];
__device__ __nv_bfloat16 g_wh[3 * NHID * NHID], g_wl[3 * NHID * NHID];   // Wq|Wk|Wv
__device__ __nv_bfloat16 g_woh[NHID * NHID], g_wol[NHID * NHID];
__device__ __nv_bfloat16 g_qh[NB * NHEADS * NS * DHEAD], g_ql[NB * NHEADS * NS * DHEAD];
__device__ __nv_bfloat16 g_kh[NB * NHEADS * NS * DHEAD], g_kl[NB * NHEADS * NS * DHEAD];
__device__ __half        g_vh[NB * NHEADS * NS * DHEAD], g_vl[NB * NHEADS * NS * DHEAD];
__device__ __nv_bfloat16 g_ah[MTOT * NHID], g_al[MTOT * NHID];

// ===========================================================================
// Helpers
// ===========================================================================
__device__ __forceinline__ uint32_t smem_to_u32(const void* p) {
    uint32_t a;
    asm("{ .reg .u64 t; cvta.to.shared.u64 t, %1; cvt.u32.u64 %0, t; }"
        : "=r"(a) : "l"(p));
    return a;
}
__device__ __forceinline__ void cp_async16(uint32_t s, const void* g) {
    asm volatile("cp.async.cg.shared.global [%0], [%1], 16;" :: "r"(s), "l"(g));
}
__device__ __forceinline__ void cp_commit() {
    asm volatile("cp.async.commit_group;" ::: "memory");
}
template <int N>
__device__ __forceinline__ void cp_wait() {
    asm volatile("cp.async.wait_group %0;" :: "n"(N) : "memory");
}
__device__ __forceinline__ void ldmatrix_x4(uint32_t& d0, uint32_t& d1,
                                            uint32_t& d2, uint32_t& d3,
                                            uint32_t addr) {
    asm volatile("ldmatrix.sync.aligned.m8n8.x4.shared.b16 {%0,%1,%2,%3}, [%4];"
        : "=r"(d0), "=r"(d1), "=r"(d2), "=r"(d3) : "r"(addr));
}
__device__ __forceinline__ void ldmatrix_x4_trans(uint32_t& d0, uint32_t& d1,
                                                  uint32_t& d2, uint32_t& d3,
                                                  uint32_t addr) {
    asm volatile("ldmatrix.sync.aligned.m8n8.x4.trans.shared.b16 {%0,%1,%2,%3}, [%4];"
        : "=r"(d0), "=r"(d1), "=r"(d2), "=r"(d3) : "r"(addr));
}
__device__ __forceinline__ void mma_bf16(float* c, const uint32_t* a,
                                         const uint32_t* b) {
    asm volatile(
        "mma.sync.aligned.m16n8k16.row.col.f32.bf16.bf16.f32 "
        "{%0,%1,%2,%3}, {%4,%5,%6,%7}, {%8,%9}, {%0,%1,%2,%3};"
        : "+f"(c[0]), "+f"(c[1]), "+f"(c[2]), "+f"(c[3])
        : "r"(a[0]), "r"(a[1]), "r"(a[2]), "r"(a[3]), "r"(b[0]), "r"(b[1]));
}
__device__ __forceinline__ void mma_f16(float* c, const uint32_t* a,
                                        const uint32_t* b) {
    asm volatile(
        "mma.sync.aligned.m16n8k16.row.col.f32.f16.f16.f32 "
        "{%0,%1,%2,%3}, {%4,%5,%6,%7}, {%8,%9}, {%0,%1,%2,%3};"
        : "+f"(c[0]), "+f"(c[1]), "+f"(c[2]), "+f"(c[3])
        : "r"(a[0]), "r"(a[1]), "r"(a[2]), "r"(a[3]), "r"(b[0]), "r"(b[1]));
}
__device__ __forceinline__ uint32_t packbf(__nv_bfloat16 x, __nv_bfloat16 y) {
    __nv_bfloat162 p; p.x = x; p.y = y;
    return *reinterpret_cast<uint32_t*>(&p);
}
__device__ __forceinline__ void split2(float x, float y,
                                       uint32_t& hi, uint32_t& lo) {
    __nv_bfloat16 hx = __float2bfloat16_rn(x);
    __nv_bfloat16 hy = __float2bfloat16_rn(y);
    hi = packbf(hx, hy);
    lo = packbf(__float2bfloat16_rn(x - __bfloat162float(hx)),
                __float2bfloat16_rn(y - __bfloat162float(hy)));
}
__device__ __forceinline__ void split4(float4 v, uint2& hi, uint2& lo) {
    split2(v.x, v.y, hi.x, lo.x);
    split2(v.z, v.w, hi.y, lo.y);
}
// fp16 pair split (for V)
__device__ __forceinline__ void split2h(float x, float y,
                                        uint32_t& hi, uint32_t& lo) {
    __half hx = __float2half_rn(x);
    __half hy = __float2half_rn(y);
    __half2 p;
    p.x = hx; p.y = hy; hi = *reinterpret_cast<uint32_t*>(&p);
    p.x = __float2half_rn(x - __half2float(hx));
    p.y = __float2half_rn(y - __half2float(hy));
    lo = *reinterpret_cast<uint32_t*>(&p);
}
// pack two floats -> f16x2 (x -> lo lane, y -> hi lane)
__device__ __forceinline__ uint32_t f2h2(float x, float y) {
    uint32_t r;
    asm("cvt.rn.f16x2.f32 %0, %1, %2;" : "=r"(r) : "f"(y), "f"(x));
    return r;
}
__device__ __forceinline__ float ex2f(float x) {
    float r;
    asm("ex2.approx.f32 %0, %1;" : "=f"(r) : "f"(x));
    return r;
}

#define L2E 1.4426950408889634f

// ===========================================================================
// Split kernel: fp32 -> bf16 hi/lo
// ===========================================================================
__global__ __launch_bounds__(256)
void split_kernel(const float* __restrict__ src,
                  __nv_bfloat16* __restrict__ h,
                  __nv_bfloat16* __restrict__ l, int n4)
{
    int i = blockIdx.x * 256 + threadIdx.x;
    if (i < n4) {
        float4 v = ((const float4*)src)[i];
        uint2 hi, lo;
        split4(v, hi, lo);
        ((uint2*)h)[i] = hi;
        ((uint2*)l)[i] = lo;
    }
}

// ===========================================================================
// All-bf16 cp.async GEMM: CTA 128x256, warp 64x64, BK=32, 3 stages.
// qkvMode=1: scatter split output into g_q (bf16, pre-scaled by 0.125*log2e),
//            g_k (bf16), g_v (fp16) in [B,NH,S,HD].
// qkvMode=0: fp32 out.
// ===========================================================================
#define GLDS 40
#define GA_BUF 10240
#define GB_BUF 20480
#define GSTAGE (2 * GA_BUF + 2 * GB_BUF)
#define GEMM_SMEM (3 * GSTAGE)

__global__ __launch_bounds__(256, 1)
void gemm_bf16_kernel(const __nv_bfloat16* __restrict__ Ah,
                      const __nv_bfloat16* __restrict__ Al,
                      const __nv_bfloat16* __restrict__ Bh,
                      const __nv_bfloat16* __restrict__ Bl,
                      float* __restrict__ Cf, int qkvMode)
{
    extern __shared__ char smc[];
    const uint32_t sb = smem_to_u32(smc);

    const int t    = threadIdx.x;
    const int lane = t & 31;
    const int wid  = t >> 5;
    const int wm   = wid & 1;
    const int wn   = wid >> 1;
    const int m0   = blockIdx.y << 7;
    const int n0   = blockIdx.x << 8;

    const int rA = lane & 15;
    const int cA = (lane >> 4) << 3;
    const int rB = (lane & 7) + ((lane >> 4) << 3);
    const int cB = lane & 8;

    auto issue = [&](int c, int stg) {
        const int k0 = c << 5;
        const uint32_t st = sb + stg * GSTAGE;
#pragma unroll
        for (int j = 0; j < 2; j++) {
            int idx = t + (j << 8);
            int row = idx >> 2, ch = idx & 3;
            uint32_t so = (uint32_t)(row * 80 + ch * 16);
            const size_t go = (size_t)(m0 + row) * NHID + k0 + ch * 8;
            cp_async16(st + so, Ah + go);
            cp_async16(st + GA_BUF + so, Al + go);
        }
#pragma unroll
        for (int j = 0; j < 4; j++) {
            int idx = t + (j << 8);
            int row = idx >> 2, ch = idx & 3;
            uint32_t so = (uint32_t)(row * 80 + ch * 16);
            const size_t go = (size_t)(n0 + row) * NHID + k0 + ch * 8;
            cp_async16(st + 2 * GA_BUF + so, Bh + go);
            cp_async16(st + 2 * GA_BUF + GB_BUF + so, Bl + go);
        }
        cp_commit();
    };

    float acc[4][8][4];
#pragma unroll
    for (int mf = 0; mf < 4; mf++)
#pragma unroll
        for (int nf = 0; nf < 8; nf++)
#pragma unroll
            for (int r = 0; r < 4; r++) acc[mf][nf][r] = 0.f;

    issue(0, 0);
    issue(1, 1);

    for (int c = 0; c < 32; ++c) {
        if (c < 31) cp_wait<1>(); else cp_wait<0>();
        __syncthreads();
        if (c + 2 < 32) issue(c + 2, (c + 2) % 3);

        const uint32_t st = sb + (c % 3) * GSTAGE;
#pragma unroll
        for (int ks = 0; ks < 2; ks++) {
            const int k0 = ks << 4;
            uint32_t ah[4][4], al[4][4];
#pragma unroll
            for (int mf = 0; mf < 4; mf++) {
                uint32_t ro = (uint32_t)((wm * 64 + mf * 16 + rA) * GLDS + k0 + cA) * 2;
                ldmatrix_x4(ah[mf][0], ah[mf][1], ah[mf][2], ah[mf][3], st + ro);
                ldmatrix_x4(al[mf][0], al[mf][1], al[mf][2], al[mf][3], st + GA_BUF + ro);
            }
#pragma unroll
            for (int p = 0; p < 4; p++) {
                uint32_t ro = (uint32_t)((wn * 64 + p * 16 + rB) * GLDS + k0 + cB) * 2;
                uint32_t h0, h1, h2, h3, e0, e1, e2, e3;
                ldmatrix_x4(h0, h1, h2, h3, st + 2 * GA_BUF + ro);
                ldmatrix_x4(e0, e1, e2, e3, st + 2 * GA_BUF + GB_BUF + ro);
                uint32_t bh0[2] = {h0, h1}, bh1[2] = {h2, h3};
                uint32_t bl0[2] = {e0, e1}, bl1[2] = {e2, e3};
#pragma unroll
                for (int mf = 0; mf < 4; mf++) {
                    mma_bf16(acc[mf][2 * p],     ah[mf], bh0);
                    mma_bf16(acc[mf][2 * p],     ah[mf], bl0);
                    mma_bf16(acc[mf][2 * p],     al[mf], bh0);
                    mma_bf16(acc[mf][2 * p + 1], ah[mf], bh1);
                    mma_bf16(acc[mf][2 * p + 1], ah[mf], bl1);
                    mma_bf16(acc[mf][2 * p + 1], al[mf], bh1);
                }
            }
        }
    }

    const int rowBase = m0 + wm * 64 + (lane >> 2);
    const int colBase = n0 + wn * 64 + ((lane & 3) << 1);

    if (qkvMode) {
        const int which = n0 >> 10;     // 0=Q 1=K 2=V (constant per CTA)
        const float sc = (which == 0) ? 0.125f * L2E : 1.0f;
#pragma unroll
        for (int mf = 0; mf < 4; mf++)
#pragma unroll
            for (int nf = 0; nf < 8; nf++) {
                int n = colBase + nf * 8;
                int r = n & 1023;
                int h = r >> 6, d = r & 63;
#pragma unroll
                for (int half = 0; half < 2; half++) {
                    int m = rowBase + mf * 16 + half * 8;
                    int b = m >> 11, s = m & (NS - 1);
                    size_t idx = ((((size_t)(b * NHEADS + h)) * NS + s) << 6) + d;
                    uint32_t hi, lo;
                    if (which == 2) {
                        split2h(acc[mf][nf][half * 2], acc[mf][nf][half * 2 + 1], hi, lo);
                        *(uint32_t*)(g_vh + idx) = hi;
                        *(uint32_t*)(g_vl + idx) = lo;
                    } else {
                        split2(acc[mf][nf][half * 2] * sc,
                               acc[mf][nf][half * 2 + 1] * sc, hi, lo);
                        if (which == 0) {
                            *(uint32_t*)(g_qh + idx) = hi;
                            *(uint32_t*)(g_ql + idx) = lo;
                        } else {
                            *(uint32_t*)(g_kh + idx) = hi;
                            *(uint32_t*)(g_kl + idx) = lo;
                        }
                    }
                }
            }
    } else {
#pragma unroll
        for (int mf = 0; mf < 4; mf++)
#pragma unroll
            for (int nf = 0; nf < 8; nf++) {
                int n = colBase + nf * 8;
#pragma unroll
                for (int half = 0; half < 2; half++) {
                    int m = rowBase + mf * 16 + half * 8;
                    *(float2*)(Cf + (size_t)m * NHID + n) =
                        make_float2(acc[mf][nf][half * 2], acc[mf][nf][half * 2 + 1]);
                }
            }
    }
}

// ===========================================================================
// Flash attention: QK bf16 3-term, softmax in log2 domain, P fp16,
// PV fp16 2-term, row-sum l via all-ones MMA.
// CTA = (b,h) x 128 q-rows, 8 warps, K-tile 128, cp.async double-buffered.
// ===========================================================================
#define KT 128
#define ALDS 72
#define ABUF (128 * 144)
#define ASTG (4 * ABUF)
#define OQH 0
#define OQL ABUF
#define OST (2 * ABUF)
#define OMSK (OST + 2 * ASTG)
#define ATTN_SMEM (OMSK + 1024)

__global__ __launch_bounds__(256, 1)
void attn_tc_kernel(const float* __restrict__ mask)
{
    extern __shared__ char smc[];
    const uint32_t sb = smem_to_u32(smc);

    const int t    = threadIdx.x;
    const int lane = t & 31;
    const int w    = t >> 5;

    const int bh = blockIdx.y;
    const int b  = bh >> 4;
    const int h  = bh & 15;
    const int q0 = blockIdx.x << 7;

    const int rA = lane & 15;
    const int cA = (lane >> 4) << 3;
    const int rB = (lane & 7) + ((lane >> 4) << 3);
    const int cB = lane & 8;
    const int c0 = (lane & 3) << 1;

    const size_t qbase  = ((size_t)bh * NS + q0) * DHEAD;
    const size_t kvbase = (size_t)bh * NS * DHEAD;

    auto issue_kv = [&](int kt, int stg) {
        const size_t base = kvbase + (size_t)kt * KT * DHEAD;
        const uint32_t st = sb + OST + stg * ASTG;
#pragma unroll
        for (int j = 0; j < 4; j++) {
            int idx = t + (j << 8);
            int row = idx >> 3, ch = idx & 7;
            uint32_t so = (uint32_t)(row * 144 + ch * 16);
            size_t go = base + row * DHEAD + ch * 8;
            cp_async16(st + 0 * ABUF + so, g_kh + go);
            cp_async16(st + 1 * ABUF + so, g_kl + go);
            cp_async16(st + 2 * ABUF + so, g_vh + go);
            cp_async16(st + 3 * ABUF + so, g_vl + go);
        }
        if (t < 32)
            cp_async16(sb + OMSK + stg * 512 + t * 16,
                       mask + (size_t)b * NS + kt * KT + t * 4);
        cp_commit();
    };

#pragma unroll
    for (int j = 0; j < 4; j++) {
        int idx = t + (j << 8);
        int row = idx >> 3, ch = idx & 7;
        uint32_t so = (uint32_t)(row * 144 + ch * 16);
        size_t go = qbase + row * DHEAD + ch * 8;
        cp_async16(sb + OQH + so, g_qh + go);
        cp_async16(sb + OQL + so, g_ql + go);
    }
    issue_kv(0, 0);

    float accs[16][4];
    float acco[8][4];
    float acco_l[4] = {0.f, 0.f, 0.f, 0.f};
    float m0 = -INFINITY, m1 = -INFINITY;
#pragma unroll
    for (int nf = 0; nf < 8; nf++)
#pragma unroll
        for (int r = 0; r < 4; r++) acco[nf][r] = 0.f;

    const uint32_t bones[2] = {0x3C003C00u, 0x3C003C00u};  // fp16 ones

    for (int kt = 0; kt < NS / KT; kt++) {
        cp_wait<0>();
        __syncthreads();
        if (kt + 1 < NS / KT) issue_kv(kt + 1, (kt + 1) & 1);

        const int stg = kt & 1;
        const uint32_t st = sb + OST + stg * ASTG;
        const float* msk = (const float*)(smc + OMSK + stg * 512);

        // ---- S = Q K^T (log2-domain: Q pre-scaled by 0.125*log2e) ----
#pragma unroll
        for (int nf = 0; nf < 16; nf++)
#pragma unroll
            for (int r = 0; r < 4; r++) accs[nf][r] = 0.f;

#pragma unroll
        for (int ks = 0; ks < 4; ks++) {
            uint32_t aqh[4], aql[4];
            uint32_t qo = (uint32_t)((w * 16 + rA) * ALDS + ks * 16 + cA) * 2;
            ldmatrix_x4(aqh[0], aqh[1], aqh[2], aqh[3], sb + OQH + qo);
            ldmatrix_x4(aql[0], aql[1], aql[2], aql[3], sb + OQL + qo);
#pragma unroll
            for (int p = 0; p < 8; p++) {
                uint32_t ko = (uint32_t)((p * 16 + rB) * ALDS + ks * 16 + cB) * 2;
                uint32_t h0, h1, h2, h3, e0, e1, e2, e3;
                ldmatrix_x4(h0, h1, h2, h3, st + 0 * ABUF + ko);
                ldmatrix_x4(e0, e1, e2, e3, st + 1 * ABUF + ko);
                uint32_t bhi0[2] = {h0, h1}, bhi1[2] = {h2, h3};
                uint32_t blo0[2] = {e0, e1}, blo1[2] = {e2, e3};
                mma_bf16(accs[2 * p],     aqh, bhi0);
                mma_bf16(accs[2 * p],     aqh, blo0);
                mma_bf16(accs[2 * p],     aql, bhi0);
                mma_bf16(accs[2 * p + 1], aqh, bhi1);
                mma_bf16(accs[2 * p + 1], aqh, blo1);
                mma_bf16(accs[2 * p + 1], aql, bhi1);
            }
        }

        // ---- + mask*log2e ----
#pragma unroll
        for (int nf = 0; nf < 16; nf++) {
            float mk0 = msk[nf * 8 + c0];
            float mk1 = msk[nf * 8 + c0 + 1];
            accs[nf][0] = fmaf(mk0, L2E, accs[nf][0]);
            accs[nf][1] = fmaf(mk1, L2E, accs[nf][1]);
            accs[nf][2] = fmaf(mk0, L2E, accs[nf][2]);
            accs[nf][3] = fmaf(mk1, L2E, accs[nf][3]);
        }

        // ---- online softmax (log2 domain) ----
        float tm0 = -INFINITY, tm1 = -INFINITY;
#pragma unroll
        for (int nf = 0; nf < 16; nf++) {
            tm0 = fmaxf(tm0, fmaxf(accs[nf][0], accs[nf][1]));
            tm1 = fmaxf(tm1, fmaxf(accs[nf][2], accs[nf][3]));
        }
        tm0 = fmaxf(tm0, __shfl_xor_sync(0xffffffffu, tm0, 1));
        tm0 = fmaxf(tm0, __shfl_xor_sync(0xffffffffu, tm0, 2));
        tm1 = fmaxf(tm1, __shfl_xor_sync(0xffffffffu, tm1, 1));
        tm1 = fmaxf(tm1, __shfl_xor_sync(0xffffffffu, tm1, 2));

        float mn0 = fmaxf(m0, tm0), mn1 = fmaxf(m1, tm1);
        float cr0 = ex2f(m0 - mn0), cr1 = ex2f(m1 - mn1);
        m0 = mn0; m1 = mn1;

#pragma unroll
        for (int nf = 0; nf < 16; nf++) {
            accs[nf][0] = ex2f(accs[nf][0] - mn0);
            accs[nf][1] = ex2f(accs[nf][1] - mn0);
            accs[nf][2] = ex2f(accs[nf][2] - mn1);
            accs[nf][3] = ex2f(accs[nf][3] - mn1);
        }

#pragma unroll
        for (int nf = 0; nf < 8; nf++) {
            acco[nf][0] *= cr0; acco[nf][1] *= cr0;
            acco[nf][2] *= cr1; acco[nf][3] *= cr1;
        }
        acco_l[0] *= cr0; acco_l[1] *= cr0;
        acco_l[2] *= cr1; acco_l[3] *= cr1;

        // ---- O += P V  (P fp16, V fp16 hi/lo, l via ones-MMA) ----
#pragma unroll
        for (int kc = 0; kc < 8; kc++) {
            uint32_t aph[4];
            aph[0] = f2h2(accs[2 * kc][0],     accs[2 * kc][1]);
            aph[1] = f2h2(accs[2 * kc][2],     accs[2 * kc][3]);
            aph[2] = f2h2(accs[2 * kc + 1][0], accs[2 * kc + 1][1]);
            aph[3] = f2h2(accs[2 * kc + 1][2], accs[2 * kc + 1][3]);
            mma_f16(acco_l, aph, bones);
#pragma unroll
            for (int pv = 0; pv < 4; pv++) {
                uint32_t vo = (uint32_t)((kc * 16 + rA) * ALDS + pv * 16 + cA) * 2;
                uint32_t h0, h1, h2, h3, e0, e1, e2, e3;
                ldmatrix_x4_trans(h0, h1, h2, h3, st + 2 * ABUF + vo);
                ldmatrix_x4_trans(e0, e1, e2, e3, st + 3 * ABUF + vo);
                uint32_t bvh0[2] = {h0, h1}, bvh1[2] = {h2, h3};
                uint32_t bvl0[2] = {e0, e1}, bvl1[2] = {e2, e3};
                mma_f16(acco[2 * pv],     aph, bvh0);
                mma_f16(acco[2 * pv],     aph, bvl0);
                mma_f16(acco[2 * pv + 1], aph, bvh1);
                mma_f16(acco[2 * pv + 1], aph, bvl1);
            }
        }
    }

    // ---- epilogue ----
    float inv0 = 1.f / acco_l[0];
    float inv1 = 1.f / acco_l[2];
    int row0 = q0 + w * 16 + (lane >> 2);
#pragma unroll
    for (int nf = 0; nf < 8; nf++) {
        int d = nf * 8 + c0;
        size_t i0 = ((size_t)(b * NS) + row0) * NHID + h * DHEAD + d;
        size_t i1 = i0 + (size_t)8 * NHID;
        uint32_t hi, lo;
        split2(acco[nf][0] * inv0, acco[nf][1] * inv0, hi, lo);
        *(uint32_t*)(g_ah + i0) = hi;
        *(uint32_t*)(g_al + i0) = lo;
        split2(acco[nf][2] * inv1, acco[nf][3] * inv1, hi, lo);
        *(uint32_t*)(g_ah + i1) = hi;
        *(uint32_t*)(g_al + i1) = lo;
    }
}

// ---------------------------------------------------------------------------
// Launch
// ---------------------------------------------------------------------------
extern "C" void kernel_launch(void* const* d_in, const int* in_sizes, int n_in,
                              void* d_out, int out_size)
{
    const float* X    = (const float*)d_in[0];
    const float* mask = (const float*)d_in[1];
    const float* Wq   = (const float*)d_in[2];
    const float* Wk   = (const float*)d_in[3];
    const float* Wv   = (const float*)d_in[4];
    const float* Wo   = (const float*)d_in[5];
    float* out = (float*)d_out;

    __nv_bfloat16 *xh, *xl, *wh, *wl, *woh, *wol, *ah, *al;
    cudaGetSymbolAddress((void**)&xh, g_xh);   cudaGetSymbolAddress((void**)&xl, g_xl);
    cudaGetSymbolAddress((void**)&wh, g_wh);   cudaGetSymbolAddress((void**)&wl, g_wl);
    cudaGetSymbolAddress((void**)&woh, g_woh); cudaGetSymbolAddress((void**)&wol, g_wol);
    cudaGetSymbolAddress((void**)&ah, g_ah);   cudaGetSymbolAddress((void**)&al, g_al);

    cudaFuncSetAttribute(gemm_bf16_kernel,
                         cudaFuncAttributeMaxDynamicSharedMemorySize, GEMM_SMEM);
    cudaFuncSetAttribute(attn_tc_kernel,
                         cudaFuncAttributeMaxDynamicSharedMemorySize, ATTN_SMEM);

    int n4x = MTOT * NHID / 4;
    int n4w = NHID * NHID / 4;
    split_kernel<<<n4x / 256, 256>>>(X,  xh,  xl,  n4x);
    split_kernel<<<n4w / 256, 256>>>(Wq, wh,               wl,               n4w);
    split_kernel<<<n4w / 256, 256>>>(Wk, wh + NHID*NHID,   wl + NHID*NHID,   n4w);
    split_kernel<<<n4w / 256, 256>>>(Wv, wh + 2*NHID*NHID, wl + 2*NHID*NHID, n4w);
    split_kernel<<<n4w / 256, 256>>>(Wo, woh, wol, n4w);

    dim3 gq(3 * NHID / 256, MTOT / 128);   // 12 x 64
    gemm_bf16_kernel<<<gq, 256, GEMM_SMEM>>>(xh, xl, wh, wl, nullptr, 1);

    dim3 ga(NS / 128, NB * NHEADS);        // 16 x 64
    attn_tc_kernel<<<ga, 256, ATTN_SMEM>>>(mask);

    dim3 go(NHID / 256, MTOT / 128);       // 4 x 64
    gemm_bf16_kernel<<<go, 256, GEMM_SMEM>>>(ah, al, woh, wol, out, 0);
}